// round 9
// baseline (speedup 1.0000x reference)
#include <cuda_runtime.h>

#define NN 4
#define CC 64
#define VV 25
#define TT 300
#define MM 2
#define HH 8
#define HD 32
#define EE 256
#define ROWS 60000   /* NN*MM*VV*TT */
#define BVH 1600     /* (NN*MM*VV) * HH */

// ---------------- device scratch (no allocations allowed) ----------------
__device__ float g_xt[(size_t)ROWS * CC];
__device__ float g_q [(size_t)ROWS * EE];
__device__ float g_k [(size_t)ROWS * EE];     // pre-scaled by 1/16
__device__ float g_v [(size_t)ROWS * EE];
__device__ float g_attn[(size_t)ROWS * EE];

__device__ __forceinline__ float tf32f(float x) {
    unsigned u;
    asm("cvt.rna.tf32.f32 %0, %1;" : "=r"(u) : "f"(x));
    return __uint_as_float(u);
}

#define MMA_TF32(c0,c1,c2,c3,a0,a1,a2,a3,b0,b1) \
    asm volatile( \
        "mma.sync.aligned.m16n8k8.row.col.f32.tf32.tf32.f32 " \
        "{%0,%1,%2,%3}, {%4,%5,%6,%7}, {%8,%9}, {%0,%1,%2,%3};\n" \
        : "+f"(c0), "+f"(c1), "+f"(c2), "+f"(c3) \
        : "r"(a0), "r"(a1), "r"(a2), "r"(a3), "r"(b0), "r"(b1))

// ldmatrix x4 viewing f32 tiles as b16 matrices (CUTLASS tf32 trick).
// A-pattern: 16 rows x 8 f32 cols -> full m16k8 A fragment {a0,a1,a2,a3}.
__device__ __forceinline__ void ldsm_a(unsigned (&r)[4], const float* base,
                                       int stride, int lane) {
    unsigned addr = (unsigned)__cvta_generic_to_shared(
        base + (lane & 15) * stride + ((lane >> 4) << 2));
    asm volatile("ldmatrix.sync.aligned.m8n8.x4.shared.b16 {%0,%1,%2,%3}, [%4];"
                 : "=r"(r[0]), "=r"(r[1]), "=r"(r[2]), "=r"(r[3]) : "r"(addr));
}
// B-pattern: 8 rows (n) x 16 f32 cols (k) -> B frags for TWO k-steps:
// {b0_ks0, b1_ks0, b0_ks1, b1_ks1}.
__device__ __forceinline__ void ldsm_b(unsigned (&r)[4], const float* base,
                                       int stride, int lane) {
    unsigned addr = (unsigned)__cvta_generic_to_shared(
        base + (lane & 7) * stride + ((lane >> 3) << 2));
    asm volatile("ldmatrix.sync.aligned.m8n8.x4.shared.b16 {%0,%1,%2,%3}, [%4];"
                 : "=r"(r[0]), "=r"(r[1]), "=r"(r[2]), "=r"(r[3]) : "r"(addr));
}

// ---------------------------------------------------------------------------
// Kernel A: transpose x (N,C,V,T,M) -> g_xt[row][c]
// ---------------------------------------------------------------------------
__global__ __launch_bounds__(256) void kernA(const float* __restrict__ x) {
    __shared__ float sm[64][33];
    int tm0 = blockIdx.x * 32;
    int v   = blockIdx.y;
    int n   = blockIdx.z;
    int tid  = threadIdx.x;
    int lane = tid & 31;
    int crow = tid >> 5;
#pragma unroll
    for (int kk = 0; kk < 8; kk++) {
        int c  = crow + (kk << 3);
        int tm = tm0 + lane;
        float val = 0.f;
        if (tm < 600) val = x[((size_t)(n * CC + c) * VV + v) * 600 + tm];
        sm[c][lane] = val;
    }
    __syncthreads();
    int c2 = tid & 63;
    int jb = tid >> 6;
#pragma unroll
    for (int kk = 0; kk < 8; kk++) {
        int j  = jb + (kk << 2);
        int tm = tm0 + j;
        if (tm < 600) {
            int t = tm >> 1, m = tm & 1;
            size_t row = ((size_t)((n * 2 + m) * VV + v)) * TT + t;
            g_xt[row * CC + c2] = sm[c2][j];
        }
    }
}

// ---------------------------------------------------------------------------
// Kernel B (tf32 mma + ldmatrix): qkv = xt @ w_qkv + b_qkv
// ---------------------------------------------------------------------------
__global__ __launch_bounds__(256) void kernB(const float* __restrict__ w,
                                             const float* __restrict__ b) {
    extern __shared__ float smB[];
    float* sxr = smB;              // 64 x 68  (A, row-major, tf32)
    float* swt = smB + 64 * 68;    // 128 x 68 (B^T: swt[n][k], tf32)
    int tid = threadIdx.x;
    int c0 = blockIdx.x * 128;
    int r0 = blockIdx.y * 64;

    for (int idx = tid; idx < 64 * 64; idx += 256) {
        int m = idx >> 6, e = idx & 63;
        int row = r0 + m;
        float v = (row < ROWS) ? g_xt[(size_t)row * CC + e] : 0.f;
        sxr[m * 68 + e] = tf32f(v);
    }
    for (int idx = tid; idx < 128 * 64; idx += 256) {
        int n = idx & 127, k = idx >> 7;
        swt[n * 68 + k] = tf32f(w[(size_t)k * 768 + c0 + n]);
    }
    __syncthreads();

    int wd = tid >> 5, lane = tid & 31;
    int gid = lane >> 2, tig = lane & 3;
    int mt = wd & 3, nh = wd >> 2;

    // A fragments: full K=64 (8 k-steps) via ldmatrix
    unsigned af[8][4];
    {
        const float* qb = sxr + (mt * 16) * 68;
#pragma unroll
        for (int ks = 0; ks < 8; ks++)
            ldsm_a(af[ks], qb + ks * 8, 68, lane);
    }

    float* dst; float scale; int cb;
    if (c0 < 256)      { dst = g_q; scale = 1.0f;    cb = c0; }
    else if (c0 < 512) { dst = g_k; scale = 0.0625f; cb = c0 - 256; }
    else               { dst = g_v; scale = 1.0f;    cb = c0 - 512; }

#pragma unroll
    for (int nt2 = 0; nt2 < 8; nt2++) {
        int n0 = (nh * 8 + nt2) * 8;
        float a0 = 0.f, a1 = 0.f, a2 = 0.f, a3 = 0.f;
        const float* bs = swt + n0 * 68;
#pragma unroll
        for (int c2 = 0; c2 < 4; c2++) {
            unsigned bb[4];
            ldsm_b(bb, bs + c2 * 16, 68, lane);
            int ks = c2 * 2;
            MMA_TF32(a0, a1, a2, a3, af[ks][0], af[ks][1], af[ks][2], af[ks][3], bb[0], bb[1]);
            MMA_TF32(a0, a1, a2, a3, af[ks+1][0], af[ks+1][1], af[ks+1][2], af[ks+1][3], bb[2], bb[3]);
        }
        int col = cb + n0 + 2 * tig;
        float bb0 = b[c0 - cb + col];
        float bb1 = b[c0 - cb + col + 1];
        int r1 = r0 + mt * 16 + gid;
        if (r1 < ROWS)
            *(float2*)&dst[(size_t)r1 * EE + col] =
                make_float2((a0 + bb0) * scale, (a1 + bb1) * scale);
        int r2 = r1 + 8;
        if (r2 < ROWS)
            *(float2*)&dst[(size_t)r2 * EE + col] =
                make_float2((a2 + bb0) * scale, (a3 + bb1) * scale);
    }
}

// ---------------------------------------------------------------------------
// Kernel Attn (all-tensor tf32 + ldmatrix): block per (bv,h), 1024 threads,
// 32-row tiles. R scatter-store, S RMW-add, warp-per-row softmax,
// PV 4-way split-K over 32 warps.
// ---------------------------------------------------------------------------
__global__ __launch_bounds__(1024, 1) void kernAttn(const float* __restrict__ bias_table) {
    extern __shared__ float smem[];
    float* sb = smem;                    // 599 x 36 (tf32)
    float* sk = sb + 599 * 36;           // 304 x 36 (tf32) rows >=300 zero
    float* sv = sk + 304 * 36;           // 304 x 32 (tf32, swizzled d'=(d+8j)&31)
    float* sq = sv + 304 * 32;           // 32 x 36 (tf32)
    float* sS = sq + 32 * 36;            // 32 x 308 scores -> probs
    float* spv = sS + 32 * 308;          // 3 x 1024 PV partials

    int head = blockIdx.x;
    int bv = head >> 3;
    int h  = head & 7;
    size_t row0 = (size_t)bv * TT;
    int tid = threadIdx.x;
    int w = tid >> 5, lane = tid & 31;
    int gid = lane >> 2, tig = lane & 3;

    for (int idx = tid; idx < 599 * 32; idx += 1024) {
        int r = idx >> 5, d = idx & 31;
        sb[r * 36 + d] = tf32f(bias_table[r * 32 + d]);
    }
    for (int idx = tid; idx < 304 * 32; idx += 1024) {
        int j = idx >> 5, d = idx & 31;
        float kv = 0.f, vv = 0.f;
        if (j < 300) {
            size_t g = (row0 + j) * EE + h * HD + d;
            kv = g_k[g];
            vv = g_v[g];
        }
        sk[j * 36 + d] = tf32f(kv);
        sv[j * 32 + ((d + 8 * j) & 31)] = tf32f(vv);
    }

    int mt   = w & 1;
    int qidx = w >> 1;

    for (int l0 = 0; l0 < TT; l0 += 32) {
        __syncthreads();
        {
            int r = tid >> 5, d = lane;
            int l = l0 + r; if (l > 299) l = 299;
            sq[r * 36 + d] = tf32f(g_q[(row0 + l) * EE + h * HD + d]);
        }
        __syncthreads();

        // A fragments for this warp's m-tile (4 k-steps)
        unsigned af[4][4];
        {
            const float* qb = sq + (mt * 16) * 36;
#pragma unroll
            for (int ks = 0; ks < 4; ks++)
                ldsm_a(af[ks], qb + ks * 8, 36, lane);
        }

        // ---- phase R: scatter-store rel-position scores ----
        for (int nt = qidx; nt < 42; nt += 16) {
            float c0 = 0.f, c1 = 0.f, c2 = 0.f, c3 = 0.f;
            const float* bsrc = sb + (l0 + 8 * nt) * 36;
            unsigned b01[4], b23[4];
            ldsm_b(b01, bsrc, 36, lane);
            ldsm_b(b23, bsrc + 16, 36, lane);
            MMA_TF32(c0, c1, c2, c3, af[0][0], af[0][1], af[0][2], af[0][3], b01[0], b01[1]);
            MMA_TF32(c0, c1, c2, c3, af[1][0], af[1][1], af[1][2], af[1][3], b01[2], b01[3]);
            MMA_TF32(c0, c1, c2, c3, af[2][0], af[2][1], af[2][2], af[2][3], b23[0], b23[1]);
            MMA_TF32(c0, c1, c2, c3, af[3][0], af[3][1], af[3][2], af[3][3], b23[2], b23[3]);
            int lr = mt * 16 + gid;
            int jb = lr + 299 - 8 * nt - 2 * tig;
            if (jb >= 0 && jb < 304)         sS[lr * 308 + jb]           = c0;
            if (jb - 1 >= 0 && jb - 1 < 304) sS[lr * 308 + jb - 1]       = c1;
            int jb8 = jb + 8;
            if (jb8 >= 0 && jb8 < 304)         sS[(lr + 8) * 308 + jb8]     = c2;
            if (jb8 - 1 >= 0 && jb8 - 1 < 304) sS[(lr + 8) * 308 + jb8 - 1] = c3;
        }
        __syncthreads();

        // ---- phase S: add Q.K^T ----
        for (int nt = qidx; nt < 38; nt += 16) {
            float c0 = 0.f, c1 = 0.f, c2 = 0.f, c3 = 0.f;
            const float* bsrc = sk + (8 * nt) * 36;
            unsigned b01[4], b23[4];
            ldsm_b(b01, bsrc, 36, lane);
            ldsm_b(b23, bsrc + 16, 36, lane);
            MMA_TF32(c0, c1, c2, c3, af[0][0], af[0][1], af[0][2], af[0][3], b01[0], b01[1]);
            MMA_TF32(c0, c1, c2, c3, af[1][0], af[1][1], af[1][2], af[1][3], b01[2], b01[3]);
            MMA_TF32(c0, c1, c2, c3, af[2][0], af[2][1], af[2][2], af[2][3], b23[0], b23[1]);
            MMA_TF32(c0, c1, c2, c3, af[3][0], af[3][1], af[3][2], af[3][3], b23[2], b23[3]);
            float* p = sS + (mt * 16 + gid) * 308 + 8 * nt + 2 * tig;
            float2 e0 = *(float2*)p;
            e0.x += c0; e0.y += c1;
            *(float2*)p = e0;
            float* p2 = p + 8 * 308;
            float2 e1 = *(float2*)p2;
            e1.x += c2; e1.y += c3;
            *(float2*)p2 = e1;
        }
        __syncthreads();

        // ---- softmax: warp w handles row w ----
        {
            int l = l0 + w;
            float* row = sS + w * 308;
            if (l < TT) {
                float sc[10];
#pragma unroll
                for (int jj = 0; jj < 10; jj++) {
                    int j = lane + (jj << 5);
                    sc[jj] = (j < TT) ? row[j] : -3.0e38f;
                }
                float mx = sc[0];
#pragma unroll
                for (int jj = 1; jj < 10; jj++) mx = fmaxf(mx, sc[jj]);
#pragma unroll
                for (int off = 16; off > 0; off >>= 1)
                    mx = fmaxf(mx, __shfl_xor_sync(0xffffffffu, mx, off));
                float s = 0.f;
#pragma unroll
                for (int jj = 0; jj < 10; jj++) {
                    int j = lane + (jj << 5);
                    float e = (j < TT) ? __expf(sc[jj] - mx) : 0.f;
                    sc[jj] = e;
                    s += e;
                }
#pragma unroll
                for (int off = 16; off > 0; off >>= 1)
                    s += __shfl_xor_sync(0xffffffffu, s, off);
                float inv = 1.0f / s;
#pragma unroll
                for (int jj = 0; jj < 10; jj++) {
                    int j = lane + (jj << 5);
                    if (j < 304) row[j] = (j < TT) ? tf32f(sc[jj] * inv) : 0.f;
                }
            } else {
#pragma unroll
                for (int jj = 0; jj < 10; jj++) {
                    int j = lane + (jj << 5);
                    if (j < 304) row[j] = 0.f;
                }
            }
        }
        __syncthreads();

        // ---- PV: all 32 warps, 4-way split-K ----
        {
            int tile = w & 7;
            int pmt  = tile & 1;
            int n0   = (tile >> 1) * 8;
            int kh   = w >> 3;
            int ksA  = kh * 10;
            int ksB  = (kh == 3) ? 38 : ksA + 10;
            float c0 = 0.f, c1 = 0.f, c2 = 0.f, c3 = 0.f;
            const float* pbase = sS + (pmt * 16) * 308;
#pragma unroll 2
            for (int ks = ksA; ks < ksB; ks++) {
                unsigned pa[4];
                ldsm_a(pa, pbase + ks * 8, 308, lane);
                int k0r = ks * 8 + tig, k1r = k0r + 4;
                unsigned b0 = __float_as_uint(sv[k0r * 32 + ((n0 + gid + 8 * k0r) & 31)]);
                unsigned b1 = __float_as_uint(sv[k1r * 32 + ((n0 + gid + 8 * k1r) & 31)]);
                MMA_TF32(c0, c1, c2, c3, pa[0], pa[1], pa[2], pa[3], b0, b1);
            }
            if (kh) {
                *(float4*)(spv + (kh - 1) * 1024 + tile * 128 + lane * 4) =
                    make_float4(c0, c1, c2, c3);
            }
            __syncthreads();
            if (kh == 0) {
                float4 p0 = *(float4*)(spv + tile * 128 + lane * 4);
                float4 p1 = *(float4*)(spv + 1024 + tile * 128 + lane * 4);
                float4 p2 = *(float4*)(spv + 2048 + tile * 128 + lane * 4);
                c0 += p0.x + p1.x + p2.x;
                c1 += p0.y + p1.y + p2.y;
                c2 += p0.z + p1.z + p2.z;
                c3 += p0.w + p1.w + p2.w;
                int r1 = l0 + pmt * 16 + gid;
                int d0 = n0 + 2 * tig;
                if (r1 < TT)
                    *(float2*)&g_attn[(row0 + r1) * EE + h * HD + d0] = make_float2(c0, c1);
                int r2 = r1 + 8;
                if (r2 < TT)
                    *(float2*)&g_attn[(row0 + r2) * EE + h * HD + d0] = make_float2(c2, c3);
            }
        }
    }
}

// ---------------------------------------------------------------------------
// Kernel Merge (tf32 mma + ldmatrix): out = attn @ w_merge + b_merge.
// Full K=256 staged once: sa[64m][260], swt[64n][260]. 8 warps = 4 m-tiles
// x 2 n-halves; each warp 16 C-frag regs over 4 n-tiles.
// ---------------------------------------------------------------------------
__global__ __launch_bounds__(256) void kernMerge(const float* __restrict__ wm,
                                                 const float* __restrict__ bm,
                                                 float* __restrict__ out) {
    extern __shared__ float smM[];
    float* sa  = smM;               // 64 x 260
    float* swt = smM + 64 * 260;    // 64 x 260
    int tid = threadIdx.x;
    int r0 = blockIdx.x * 64;

    // fill A (float4 loads)
    for (int idx = tid; idx < 64 * 64; idx += 256) {
        int m = idx >> 6, k4 = idx & 63;
        int row = r0 + m;
        float4 v = make_float4(0.f, 0.f, 0.f, 0.f);
        if (row < ROWS) v = *(const float4*)&g_attn[(size_t)row * EE + k4 * 4];
        float* d = sa + m * 260 + k4 * 4;
        d[0] = tf32f(v.x); d[1] = tf32f(v.y); d[2] = tf32f(v.z); d[3] = tf32f(v.w);
    }
    // fill W^T
    for (int idx = tid; idx < 256 * 64; idx += 256) {
        int k = idx >> 6, n = idx & 63;
        swt[n * 260 + k] = tf32f(wm[(size_t)k * CC + n]);
    }
    __syncthreads();

    int wd = tid >> 5, lane = tid & 31;
    int gid = lane >> 2, tig = lane & 3;
    int mt = wd & 3, nh = wd >> 2;

    float acc[4][4];
#pragma unroll
    for (int nt = 0; nt < 4; nt++)
#pragma unroll
        for (int i = 0; i < 4; i++) acc[nt][i] = 0.f;

    const float* abase = sa + (mt * 16) * 260;
#pragma unroll 4
    for (int kp = 0; kp < 16; kp++) {     // 2 k-steps per iteration
        unsigned a0[4], a1[4];
        ldsm_a(a0, abase + kp * 16, 260, lane);
        ldsm_a(a1, abase + kp * 16 + 8, 260, lane);
#pragma unroll
        for (int nt = 0; nt < 4; nt++) {
            unsigned bb[4];
            ldsm_b(bb, swt + (nh * 32 + nt * 8) * 260 + kp * 16, 260, lane);
            MMA_TF32(acc[nt][0], acc[nt][1], acc[nt][2], acc[nt][3],
                     a0[0], a0[1], a0[2], a0[3], bb[0], bb[1]);
            MMA_TF32(acc[nt][0], acc[nt][1], acc[nt][2], acc[nt][3],
                     a1[0], a1[1], a1[2], a1[3], bb[2], bb[3]);
        }
    }

#pragma unroll
    for (int nt = 0; nt < 4; nt++) {
        int col = nh * 32 + nt * 8 + 2 * tig;
        float bb0 = bm[col], bb1 = bm[col + 1];
#pragma unroll
        for (int half = 0; half < 2; half++) {
            int row = r0 + mt * 16 + gid + half * 8;
            if (row < ROWS) {
                int t  = row % 300;
                int vv = row / 300;
                int v  = vv % 25;
                int nm = vv / 25;
                int m  = nm & 1;
                int n  = nm >> 1;
                float o0 = acc[nt][half * 2 + 0] + bb0;
                float o1 = acc[nt][half * 2 + 1] + bb1;
                out[(((size_t)(n * CC + col) * VV + v) * TT + t) * MM + m] = o0;
                out[(((size_t)(n * CC + col + 1) * VV + v) * TT + t) * MM + m] = o1;
            }
        }
    }
}

// ---------------------------------------------------------------------------
extern "C" void kernel_launch(void* const* d_in, const int* in_sizes, int n_in,
                              void* d_out, int out_size) {
    const float* x          = (const float*)d_in[0];
    const float* w_qkv      = (const float*)d_in[1];
    const float* b_qkv      = (const float*)d_in[2];
    const float* w_merge    = (const float*)d_in[3];
    const float* b_merge    = (const float*)d_in[4];
    const float* bias_table = (const float*)d_in[5];
    float* out = (float*)d_out;

    int smem_attn  = (599 * 36 + 304 * 36 + 304 * 32 + 32 * 36 + 32 * 308 + 3 * 1024) * 4;
    int smem_b     = (64 * 68 + 128 * 68) * 4;
    int smem_merge = (2 * 64 * 260) * 4;
    cudaFuncSetAttribute(kernAttn,  cudaFuncAttributeMaxDynamicSharedMemorySize, smem_attn);
    cudaFuncSetAttribute(kernB,     cudaFuncAttributeMaxDynamicSharedMemorySize, smem_b);
    cudaFuncSetAttribute(kernMerge, cudaFuncAttributeMaxDynamicSharedMemorySize, smem_merge);

    kernA<<<dim3(19, 25, 4), 256>>>(x);
    kernB<<<dim3(6, 938), 256, smem_b>>>(w_qkv, b_qkv);
    kernAttn<<<BVH, 1024, smem_attn>>>(bias_table);
    kernMerge<<<938, 256, smem_merge>>>(w_merge, b_merge, out);
}

// round 10
// speedup vs baseline: 1.1256x; 1.1256x over previous
#include <cuda_runtime.h>
#include <cuda_fp16.h>

#define NN 4
#define CC 64
#define VV 25
#define TT 300
#define MM 2
#define HH 8
#define HD 32
#define EE 256
#define ROWS 60000   /* NN*MM*VV*TT */
#define BVH 1600     /* (NN*MM*VV) * HH */

// ---------------- device scratch (no allocations allowed) ----------------
__device__ float g_xt[(size_t)ROWS * CC];
__device__ float g_q [(size_t)ROWS * EE];
__device__ float g_k [(size_t)ROWS * EE];     // pre-scaled by 1/16
__device__ float g_v [(size_t)ROWS * EE];
__device__ float g_attn[(size_t)ROWS * EE];

__device__ __forceinline__ float tf32f(float x) {
    unsigned u;
    asm("cvt.rna.tf32.f32 %0, %1;" : "=r"(u) : "f"(x));
    return __uint_as_float(u);
}

#define MMA_TF32(c0,c1,c2,c3,a0,a1,a2,a3,b0,b1) \
    asm volatile( \
        "mma.sync.aligned.m16n8k8.row.col.f32.tf32.tf32.f32 " \
        "{%0,%1,%2,%3}, {%4,%5,%6,%7}, {%8,%9}, {%0,%1,%2,%3};\n" \
        : "+f"(c0), "+f"(c1), "+f"(c2), "+f"(c3) \
        : "r"(a0), "r"(a1), "r"(a2), "r"(a3), "r"(b0), "r"(b1))

#define MMA_F16(c0,c1,c2,c3,a0,a1,a2,a3,b0,b1) \
    asm volatile( \
        "mma.sync.aligned.m16n8k16.row.col.f32.f16.f16.f32 " \
        "{%0,%1,%2,%3}, {%4,%5,%6,%7}, {%8,%9}, {%0,%1,%2,%3};\n" \
        : "+f"(c0), "+f"(c1), "+f"(c2), "+f"(c3) \
        : "r"(a0), "r"(a1), "r"(a2), "r"(a3), "r"(b0), "r"(b1))

// ---- f32-as-b16 ldmatrix (tf32 path, kernB only) ----
__device__ __forceinline__ void ldsm_a(unsigned (&r)[4], const float* base,
                                       int stride, int lane) {
    unsigned addr = (unsigned)__cvta_generic_to_shared(
        base + (lane & 15) * stride + ((lane >> 4) << 2));
    asm volatile("ldmatrix.sync.aligned.m8n8.x4.shared.b16 {%0,%1,%2,%3}, [%4];"
                 : "=r"(r[0]), "=r"(r[1]), "=r"(r[2]), "=r"(r[3]) : "r"(addr));
}
__device__ __forceinline__ void ldsm_b(unsigned (&r)[4], const float* base,
                                       int stride, int lane) {
    unsigned addr = (unsigned)__cvta_generic_to_shared(
        base + (lane & 7) * stride + ((lane >> 3) << 2));
    asm volatile("ldmatrix.sync.aligned.m8n8.x4.shared.b16 {%0,%1,%2,%3}, [%4];"
                 : "=r"(r[0]), "=r"(r[1]), "=r"(r[2]), "=r"(r[3]) : "r"(addr));
}

// ---- genuine b16 ldmatrix (fp16 attention path) ----
// A m16k16: rows (lane&15), col half-offset ((lane>>4)*8)
__device__ __forceinline__ void ldsm_a16(unsigned (&r)[4], const __half* base,
                                         int stride, int lane) {
    unsigned addr = (unsigned)__cvta_generic_to_shared(
        base + (lane & 15) * stride + ((lane >> 4) << 3));
    asm volatile("ldmatrix.sync.aligned.m8n8.x4.shared.b16 {%0,%1,%2,%3}, [%4];"
                 : "=r"(r[0]), "=r"(r[1]), "=r"(r[2]), "=r"(r[3]) : "r"(addr));
}
// B from bt[n][k] rows: one x4 = B frags for k=0..31 (2 k16-steps)
__device__ __forceinline__ void ldsm_b16(unsigned (&r)[4], const __half* base,
                                         int stride, int lane) {
    unsigned addr = (unsigned)__cvta_generic_to_shared(
        base + (lane & 7) * stride + ((lane >> 3) << 3));
    asm volatile("ldmatrix.sync.aligned.m8n8.x4.shared.b16 {%0,%1,%2,%3}, [%4];"
                 : "=r"(r[0]), "=r"(r[1]), "=r"(r[2]), "=r"(r[3]) : "r"(addr));
}
// B from V[k=j][n=d] rows via .trans: one x4 = B frags for one k16-step,
// TWO n-tiles (cols d0..d0+7 and d0+8..d0+15)
__device__ __forceinline__ void ldsm_bt16(unsigned (&r)[4], const __half* base,
                                          int stride, int lane) {
    unsigned addr = (unsigned)__cvta_generic_to_shared(
        base + (lane & 15) * stride + ((lane >> 4) << 3));
    asm volatile("ldmatrix.sync.aligned.m8n8.x4.trans.shared.b16 {%0,%1,%2,%3}, [%4];"
                 : "=r"(r[0]), "=r"(r[1]), "=r"(r[2]), "=r"(r[3]) : "r"(addr));
}

// dummy kernel: shifts ncu's skip-count so kernAttn gets profiled
__global__ void kernNop() {}

// ---------------------------------------------------------------------------
// Kernel A: transpose x (N,C,V,T,M) -> g_xt[row][c]
// ---------------------------------------------------------------------------
__global__ __launch_bounds__(256) void kernA(const float* __restrict__ x) {
    __shared__ float sm[64][33];
    int tm0 = blockIdx.x * 32;
    int v   = blockIdx.y;
    int n   = blockIdx.z;
    int tid  = threadIdx.x;
    int lane = tid & 31;
    int crow = tid >> 5;
#pragma unroll
    for (int kk = 0; kk < 8; kk++) {
        int c  = crow + (kk << 3);
        int tm = tm0 + lane;
        float val = 0.f;
        if (tm < 600) val = x[((size_t)(n * CC + c) * VV + v) * 600 + tm];
        sm[c][lane] = val;
    }
    __syncthreads();
    int c2 = tid & 63;
    int jb = tid >> 6;
#pragma unroll
    for (int kk = 0; kk < 8; kk++) {
        int j  = jb + (kk << 2);
        int tm = tm0 + j;
        if (tm < 600) {
            int t = tm >> 1, m = tm & 1;
            size_t row = ((size_t)((n * 2 + m) * VV + v)) * TT + t;
            g_xt[row * CC + c2] = sm[c2][j];
        }
    }
}

// ---------------------------------------------------------------------------
// Kernel B (tf32 mma + ldmatrix): qkv = xt @ w_qkv + b_qkv
// ---------------------------------------------------------------------------
__global__ __launch_bounds__(256) void kernB(const float* __restrict__ w,
                                             const float* __restrict__ b) {
    extern __shared__ float smB[];
    float* sxr = smB;              // 64 x 68  (A, row-major, tf32)
    float* swt = smB + 64 * 68;    // 128 x 68 (B^T: swt[n][k], tf32)
    int tid = threadIdx.x;
    int c0 = blockIdx.x * 128;
    int r0 = blockIdx.y * 64;

    for (int idx = tid; idx < 64 * 64; idx += 256) {
        int m = idx >> 6, e = idx & 63;
        int row = r0 + m;
        float v = (row < ROWS) ? g_xt[(size_t)row * CC + e] : 0.f;
        sxr[m * 68 + e] = tf32f(v);
    }
    for (int idx = tid; idx < 128 * 64; idx += 256) {
        int n = idx & 127, k = idx >> 7;
        swt[n * 68 + k] = tf32f(w[(size_t)k * 768 + c0 + n]);
    }
    __syncthreads();

    int wd = tid >> 5, lane = tid & 31;
    int gid = lane >> 2, tig = lane & 3;
    int mt = wd & 3, nh = wd >> 2;

    unsigned af[8][4];
    {
        const float* qb = sxr + (mt * 16) * 68;
#pragma unroll
        for (int ks = 0; ks < 8; ks++)
            ldsm_a(af[ks], qb + ks * 8, 68, lane);
    }

    float* dst; float scale; int cb;
    if (c0 < 256)      { dst = g_q; scale = 1.0f;    cb = c0; }
    else if (c0 < 512) { dst = g_k; scale = 0.0625f; cb = c0 - 256; }
    else               { dst = g_v; scale = 1.0f;    cb = c0 - 512; }

#pragma unroll
    for (int nt2 = 0; nt2 < 8; nt2++) {
        int n0 = (nh * 8 + nt2) * 8;
        float a0 = 0.f, a1 = 0.f, a2 = 0.f, a3 = 0.f;
        const float* bs = swt + n0 * 68;
#pragma unroll
        for (int c2 = 0; c2 < 4; c2++) {
            unsigned bb[4];
            ldsm_b(bb, bs + c2 * 16, 68, lane);
            int ks = c2 * 2;
            MMA_TF32(a0, a1, a2, a3, af[ks][0], af[ks][1], af[ks][2], af[ks][3], bb[0], bb[1]);
            MMA_TF32(a0, a1, a2, a3, af[ks+1][0], af[ks+1][1], af[ks+1][2], af[ks+1][3], bb[2], bb[3]);
        }
        int col = cb + n0 + 2 * tig;
        float bb0 = b[c0 - cb + col];
        float bb1 = b[c0 - cb + col + 1];
        int r1 = r0 + mt * 16 + gid;
        if (r1 < ROWS)
            *(float2*)&dst[(size_t)r1 * EE + col] =
                make_float2((a0 + bb0) * scale, (a1 + bb1) * scale);
        int r2 = r1 + 8;
        if (r2 < ROWS)
            *(float2*)&dst[(size_t)r2 * EE + col] =
                make_float2((a2 + bb0) * scale, (a3 + bb1) * scale);
    }
}

// ---------------------------------------------------------------------------
// Kernel Attn (fp16 m16n8k16): block per (bv,h), 1024 threads, 32-row tiles.
// R scatter-store (f32 scores), S RMW-add, warp-per-row softmax writing fp16
// probs, PV via fp16 mma with .trans V loads, 4 tiles x 8-way split-K.
// ---------------------------------------------------------------------------
__global__ __launch_bounds__(1024, 1) void kernAttn(const float* __restrict__ bias_table) {
    extern __shared__ char smemraw[];
    __half* sbh = (__half*)smemraw;          // 599 x 40 (rows beyond 599 alias skh; outputs discarded)
    __half* skh = sbh + 599 * 40;            // 304 x 40, rows >=300 zero
    __half* svh = skh + 304 * 40;            // 304 x 40, rows >=300 zero  (V[j][d])
    __half* sqh = svh + 304 * 40;            // 32 x 40
    float*  sS  = (float*)(sqh + 32 * 40);   // 32 x 308 f32 scores
    float*  spv = sS + 32 * 308;             // 7 x 1024 PV split-K partials
    __half* sPh = (__half*)(spv + 7 * 1024); // 32 x 312 fp16 probs (cols>=300 zero)

    int head = blockIdx.x;
    int bv = head >> 3;
    int h  = head & 7;
    size_t row0 = (size_t)bv * TT;
    int tid = threadIdx.x;
    int w = tid >> 5, lane = tid & 31;
    int gid = lane >> 2, tig = lane & 3;

    for (int idx = tid; idx < 599 * 32; idx += 1024) {
        int r = idx >> 5, d = idx & 31;
        sbh[r * 40 + d] = __float2half(bias_table[r * 32 + d]);
    }
    for (int idx = tid; idx < 304 * 32; idx += 1024) {
        int j = idx >> 5, d = idx & 31;
        float kv = 0.f, vv = 0.f;
        if (j < 300) {
            size_t g = (row0 + j) * EE + h * HD + d;
            kv = g_k[g];
            vv = g_v[g];
        }
        skh[j * 40 + d] = __float2half(kv);
        svh[j * 40 + d] = __float2half(vv);
    }

    int mt   = w & 1;
    int qidx = w >> 1;

    for (int l0 = 0; l0 < TT; l0 += 32) {
        __syncthreads();
        {
            int r = tid >> 5, d = lane;
            int l = l0 + r; if (l > 299) l = 299;
            sqh[r * 40 + d] = __float2half(g_q[(row0 + l) * EE + h * HD + d]);
        }
        __syncthreads();

        // A fragments: 2 k16-steps covering d=0..31
        unsigned afA[2][4];
        {
            const __half* qb = sqh + (mt * 16) * 40;
            ldsm_a16(afA[0], qb, 40, lane);
            ldsm_a16(afA[1], qb + 16, 40, lane);
        }

        // ---- phase R: scatter-store rel-position scores ----
        for (int nt = qidx; nt < 42; nt += 16) {
            float c0 = 0.f, c1 = 0.f, c2 = 0.f, c3 = 0.f;
            const __half* bsrc = sbh + (l0 + 8 * nt) * 40;
            unsigned bf[4];
            ldsm_b16(bf, bsrc, 40, lane);
            MMA_F16(c0, c1, c2, c3, afA[0][0], afA[0][1], afA[0][2], afA[0][3], bf[0], bf[1]);
            MMA_F16(c0, c1, c2, c3, afA[1][0], afA[1][1], afA[1][2], afA[1][3], bf[2], bf[3]);
            int lr = mt * 16 + gid;
            int jb = lr + 299 - 8 * nt - 2 * tig;
            if (jb >= 0 && jb < 304)         sS[lr * 308 + jb]           = c0;
            if (jb - 1 >= 0 && jb - 1 < 304) sS[lr * 308 + jb - 1]       = c1;
            int jb8 = jb + 8;
            if (jb8 >= 0 && jb8 < 304)         sS[(lr + 8) * 308 + jb8]     = c2;
            if (jb8 - 1 >= 0 && jb8 - 1 < 304) sS[(lr + 8) * 308 + jb8 - 1] = c3;
        }
        __syncthreads();

        // ---- phase S: add Q.K^T ----
        for (int nt = qidx; nt < 38; nt += 16) {
            float c0 = 0.f, c1 = 0.f, c2 = 0.f, c3 = 0.f;
            const __half* bsrc = skh + (8 * nt) * 40;
            unsigned bf[4];
            ldsm_b16(bf, bsrc, 40, lane);
            MMA_F16(c0, c1, c2, c3, afA[0][0], afA[0][1], afA[0][2], afA[0][3], bf[0], bf[1]);
            MMA_F16(c0, c1, c2, c3, afA[1][0], afA[1][1], afA[1][2], afA[1][3], bf[2], bf[3]);
            float* p = sS + (mt * 16 + gid) * 308 + 8 * nt + 2 * tig;
            float2 e0 = *(float2*)p;
            e0.x += c0; e0.y += c1;
            *(float2*)p = e0;
            float* p2 = p + 8 * 308;
            float2 e1 = *(float2*)p2;
            e1.x += c2; e1.y += c3;
            *(float2*)p2 = e1;
        }
        __syncthreads();

        // ---- softmax: warp w handles row w; probs -> fp16 sPh ----
        {
            int l = l0 + w;
            const float* row = sS + w * 308;
            __half* prow = sPh + w * 312;
            if (l < TT) {
                float sc[10];
#pragma unroll
                for (int jj = 0; jj < 10; jj++) {
                    int j = lane + (jj << 5);
                    sc[jj] = (j < TT) ? row[j] : -3.0e38f;
                }
                float mx = sc[0];
#pragma unroll
                for (int jj = 1; jj < 10; jj++) mx = fmaxf(mx, sc[jj]);
#pragma unroll
                for (int off = 16; off > 0; off >>= 1)
                    mx = fmaxf(mx, __shfl_xor_sync(0xffffffffu, mx, off));
                float s = 0.f;
#pragma unroll
                for (int jj = 0; jj < 10; jj++) {
                    int j = lane + (jj << 5);
                    float e = (j < TT) ? __expf(sc[jj] - mx) : 0.f;
                    sc[jj] = e;
                    s += e;
                }
#pragma unroll
                for (int off = 16; off > 0; off >>= 1)
                    s += __shfl_xor_sync(0xffffffffu, s, off);
                float inv = 1.0f / s;
#pragma unroll
                for (int jj = 0; jj < 10; jj++) {
                    int j = lane + (jj << 5);
                    if (j < 312) prow[j] = __float2half((j < TT) ? sc[jj] * inv : 0.f);
                }
            } else {
#pragma unroll
                for (int jj = 0; jj < 10; jj++) {
                    int j = lane + (jj << 5);
                    if (j < 312) prow[j] = __float2half(0.f);
                }
            }
        }
        __syncthreads();

        // ---- PV: 4 output tiles (pmt x d-half16) x 8-way split-K ----
        {
            int tile = w & 3;
            int pmt  = tile & 1;
            int d0   = (tile >> 1) * 16;
            int kh   = w >> 2;                  // 0..7
            int ksA  = (kh * 19) >> 3;
            int ksB  = ((kh + 1) * 19) >> 3;
            float c0 = 0.f, c1 = 0.f, c2 = 0.f, c3 = 0.f;
            float c4 = 0.f, c5 = 0.f, c6 = 0.f, c7 = 0.f;
            const __half* pbase = sPh + (pmt * 16) * 312;
            for (int ks = ksA; ks < ksB; ks++) {
                unsigned pa[4], vb[4];
                ldsm_a16(pa, pbase + ks * 16, 312, lane);
                ldsm_bt16(vb, svh + (ks * 16) * 40 + d0, 40, lane);
                MMA_F16(c0, c1, c2, c3, pa[0], pa[1], pa[2], pa[3], vb[0], vb[1]);
                MMA_F16(c4, c5, c6, c7, pa[0], pa[1], pa[2], pa[3], vb[2], vb[3]);
            }
            if (kh) {
                float* dstp = spv + (kh - 1) * 1024 + tile * 256 + lane * 8;
                *(float4*)dstp       = make_float4(c0, c1, c2, c3);
                *(float4*)(dstp + 4) = make_float4(c4, c5, c6, c7);
            }
            __syncthreads();
            if (kh == 0) {
#pragma unroll
                for (int g = 0; g < 7; g++) {
                    const float* sp = spv + g * 1024 + tile * 256 + lane * 8;
                    float4 p0 = *(const float4*)sp;
                    float4 p1 = *(const float4*)(sp + 4);
                    c0 += p0.x; c1 += p0.y; c2 += p0.z; c3 += p0.w;
                    c4 += p1.x; c5 += p1.y; c6 += p1.z; c7 += p1.w;
                }
                int r1 = l0 + pmt * 16 + gid;
                int db = h * HD + d0 + 2 * tig;
                if (r1 < TT) {
                    *(float2*)&g_attn[(row0 + r1) * EE + db]     = make_float2(c0, c1);
                    *(float2*)&g_attn[(row0 + r1) * EE + db + 8] = make_float2(c4, c5);
                }
                int r2 = r1 + 8;
                if (r2 < TT) {
                    *(float2*)&g_attn[(row0 + r2) * EE + db]     = make_float2(c2, c3);
                    *(float2*)&g_attn[(row0 + r2) * EE + db + 8] = make_float2(c6, c7);
                }
            }
        }
    }
}

// ---------------------------------------------------------------------------
// Kernel Merge (fp32 register-tiled, reverted): out = attn @ w_merge + b_merge
// ---------------------------------------------------------------------------
__global__ __launch_bounds__(256) void kernMerge(const float* __restrict__ wm,
                                                 const float* __restrict__ bm,
                                                 float* __restrict__ out) {
    __shared__ float sa[64 * 68];
    __shared__ float sw[64 * 68];
    int tid = threadIdx.x;
    int r0 = blockIdx.x * 64;
    int tx = tid & 15, ty = tid >> 4;

    float acc[4][4];
#pragma unroll
    for (int i = 0; i < 4; i++)
#pragma unroll
        for (int j = 0; j < 4; j++)
            acc[i][j] = bm[tx * 4 + j];

    for (int e0 = 0; e0 < 256; e0 += 64) {
        __syncthreads();
#pragma unroll
        for (int p = 0; p < 16; p++) {
            int idx = tid + p * 256;
            int a = idx >> 6;
            int e = idx & 63;
            int row = r0 + a;
            float va = 0.f;
            if (row < ROWS) va = g_attn[(size_t)row * EE + e0 + e];
            sa[e * 68 + a] = va;
            sw[a * 68 + e] = wm[(size_t)(e0 + a) * CC + e];
        }
        __syncthreads();
#pragma unroll
        for (int e = 0; e < 64; e++) {
            float4 a4 = *(const float4*)&sa[e * 68 + ty * 4];
            float4 b4 = *(const float4*)&sw[e * 68 + tx * 4];
            float av[4] = {a4.x, a4.y, a4.z, a4.w};
            float bv[4] = {b4.x, b4.y, b4.z, b4.w};
#pragma unroll
            for (int i = 0; i < 4; i++)
#pragma unroll
                for (int j = 0; j < 4; j++)
                    acc[i][j] = fmaf(av[i], bv[j], acc[i][j]);
        }
    }
#pragma unroll
    for (int i = 0; i < 4; i++) {
        int row = r0 + ty * 4 + i;
        if (row < ROWS) {
            int t  = row % 300;
            int vv = row / 300;
            int v  = vv % 25;
            int nm = vv / 25;
            int m  = nm & 1;
            int n  = nm >> 1;
#pragma unroll
            for (int j = 0; j < 4; j++) {
                int c = tx * 4 + j;
                out[(((size_t)(n * CC + c) * VV + v) * TT + t) * MM + m] = acc[i][j];
            }
        }
    }
}

// ---------------------------------------------------------------------------
extern "C" void kernel_launch(void* const* d_in, const int* in_sizes, int n_in,
                              void* d_out, int out_size) {
    const float* x          = (const float*)d_in[0];
    const float* w_qkv      = (const float*)d_in[1];
    const float* b_qkv      = (const float*)d_in[2];
    const float* w_merge    = (const float*)d_in[3];
    const float* b_merge    = (const float*)d_in[4];
    const float* bias_table = (const float*)d_in[5];
    float* out = (float*)d_out;

    int smem_attn = (599 * 40 + 304 * 40 * 2 + 32 * 40) * 2
                  + (32 * 308 + 7 * 1024) * 4
                  + 32 * 312 * 2;
    int smem_b    = (64 * 68 + 128 * 68) * 4;
    cudaFuncSetAttribute(kernAttn, cudaFuncAttributeMaxDynamicSharedMemorySize, smem_attn);
    cudaFuncSetAttribute(kernB,    cudaFuncAttributeMaxDynamicSharedMemorySize, smem_b);

    // three no-op launches: shift ncu's -s 5 window onto kernAttn
    kernNop<<<1, 32>>>();
    kernNop<<<1, 32>>>();
    kernNop<<<1, 32>>>();

    kernA<<<dim3(19, 25, 4), 256>>>(x);
    kernB<<<dim3(6, 938), 256, smem_b>>>(w_qkv, b_qkv);
    kernAttn<<<BVH, 1024, smem_attn>>>(bias_table);
    kernMerge<<<938, 256>>>(w_merge, b_merge, out);
}

// round 11
// speedup vs baseline: 1.1600x; 1.0306x over previous
#include <cuda_runtime.h>
#include <cuda_fp16.h>

#define NN 4
#define CC 64
#define VV 25
#define TT 300
#define MM 2
#define HH 8
#define HD 32
#define EE 256
#define ROWS 60000   /* NN*MM*VV*TT */
#define BVH 1600     /* (NN*MM*VV) * HH */

// ---------------- device scratch (no allocations allowed) ----------------
__device__ float g_xt[(size_t)ROWS * CC];
__device__ float g_q [(size_t)ROWS * EE];
__device__ float g_k [(size_t)ROWS * EE];     // pre-scaled by 1/16
__device__ float g_v [(size_t)ROWS * EE];
__device__ float g_attn[(size_t)ROWS * EE];

__device__ __forceinline__ float tf32f(float x) {
    unsigned u;
    asm("cvt.rna.tf32.f32 %0, %1;" : "=r"(u) : "f"(x));
    return __uint_as_float(u);
}

#define MMA_TF32(c0,c1,c2,c3,a0,a1,a2,a3,b0,b1) \
    asm volatile( \
        "mma.sync.aligned.m16n8k8.row.col.f32.tf32.tf32.f32 " \
        "{%0,%1,%2,%3}, {%4,%5,%6,%7}, {%8,%9}, {%0,%1,%2,%3};\n" \
        : "+f"(c0), "+f"(c1), "+f"(c2), "+f"(c3) \
        : "r"(a0), "r"(a1), "r"(a2), "r"(a3), "r"(b0), "r"(b1))

#define MMA_F16(c0,c1,c2,c3,a0,a1,a2,a3,b0,b1) \
    asm volatile( \
        "mma.sync.aligned.m16n8k16.row.col.f32.f16.f16.f32 " \
        "{%0,%1,%2,%3}, {%4,%5,%6,%7}, {%8,%9}, {%0,%1,%2,%3};\n" \
        : "+f"(c0), "+f"(c1), "+f"(c2), "+f"(c3) \
        : "r"(a0), "r"(a1), "r"(a2), "r"(a3), "r"(b0), "r"(b1))

// ---- f32-as-b16 ldmatrix (tf32 path, kernB only) ----
__device__ __forceinline__ void ldsm_a(unsigned (&r)[4], const float* base,
                                       int stride, int lane) {
    unsigned addr = (unsigned)__cvta_generic_to_shared(
        base + (lane & 15) * stride + ((lane >> 4) << 2));
    asm volatile("ldmatrix.sync.aligned.m8n8.x4.shared.b16 {%0,%1,%2,%3}, [%4];"
                 : "=r"(r[0]), "=r"(r[1]), "=r"(r[2]), "=r"(r[3]) : "r"(addr));
}
__device__ __forceinline__ void ldsm_b(unsigned (&r)[4], const float* base,
                                       int stride, int lane) {
    unsigned addr = (unsigned)__cvta_generic_to_shared(
        base + (lane & 7) * stride + ((lane >> 3) << 2));
    asm volatile("ldmatrix.sync.aligned.m8n8.x4.shared.b16 {%0,%1,%2,%3}, [%4];"
                 : "=r"(r[0]), "=r"(r[1]), "=r"(r[2]), "=r"(r[3]) : "r"(addr));
}

// ---- genuine b16 ldmatrix (fp16 attention path) ----
__device__ __forceinline__ void ldsm_a16(unsigned (&r)[4], const __half* base,
                                         int stride, int lane) {
    unsigned addr = (unsigned)__cvta_generic_to_shared(
        base + (lane & 15) * stride + ((lane >> 4) << 3));
    asm volatile("ldmatrix.sync.aligned.m8n8.x4.shared.b16 {%0,%1,%2,%3}, [%4];"
                 : "=r"(r[0]), "=r"(r[1]), "=r"(r[2]), "=r"(r[3]) : "r"(addr));
}
// B from bt[n][k] rows: one x4 = B frags for k=0..31 (2 k16-steps)
__device__ __forceinline__ void ldsm_b16(unsigned (&r)[4], const __half* base,
                                         int stride, int lane) {
    unsigned addr = (unsigned)__cvta_generic_to_shared(
        base + (lane & 7) * stride + ((lane >> 3) << 3));
    asm volatile("ldmatrix.sync.aligned.m8n8.x4.shared.b16 {%0,%1,%2,%3}, [%4];"
                 : "=r"(r[0]), "=r"(r[1]), "=r"(r[2]), "=r"(r[3]) : "r"(addr));
}
// B from V[k=j][n=d] rows via .trans: one x4 = B frags for one k16-step,
// TWO n-tiles (cols d0..d0+7 and d0+8..d0+15)
__device__ __forceinline__ void ldsm_bt16(unsigned (&r)[4], const __half* base,
                                          int stride, int lane) {
    unsigned addr = (unsigned)__cvta_generic_to_shared(
        base + (lane & 15) * stride + ((lane >> 4) << 3));
    asm volatile("ldmatrix.sync.aligned.m8n8.x4.trans.shared.b16 {%0,%1,%2,%3}, [%4];"
                 : "=r"(r[0]), "=r"(r[1]), "=r"(r[2]), "=r"(r[3]) : "r"(addr));
}

// dummy kernel: shifts ncu's skip-count so kernAttn gets profiled
__global__ void kernNop() {}

// ---------------------------------------------------------------------------
// Kernel A: transpose x (N,C,V,T,M) -> g_xt[row][c]
// ---------------------------------------------------------------------------
__global__ __launch_bounds__(256) void kernA(const float* __restrict__ x) {
    __shared__ float sm[64][33];
    int tm0 = blockIdx.x * 32;
    int v   = blockIdx.y;
    int n   = blockIdx.z;
    int tid  = threadIdx.x;
    int lane = tid & 31;
    int crow = tid >> 5;
#pragma unroll
    for (int kk = 0; kk < 8; kk++) {
        int c  = crow + (kk << 3);
        int tm = tm0 + lane;
        float val = 0.f;
        if (tm < 600) val = x[((size_t)(n * CC + c) * VV + v) * 600 + tm];
        sm[c][lane] = val;
    }
    __syncthreads();
    int c2 = tid & 63;
    int jb = tid >> 6;
#pragma unroll
    for (int kk = 0; kk < 8; kk++) {
        int j  = jb + (kk << 2);
        int tm = tm0 + j;
        if (tm < 600) {
            int t = tm >> 1, m = tm & 1;
            size_t row = ((size_t)((n * 2 + m) * VV + v)) * TT + t;
            g_xt[row * CC + c2] = sm[c2][j];
        }
    }
}

// ---------------------------------------------------------------------------
// Kernel B (tf32 mma + ldmatrix): qkv = xt @ w_qkv + b_qkv
// ---------------------------------------------------------------------------
__global__ __launch_bounds__(256) void kernB(const float* __restrict__ w,
                                             const float* __restrict__ b) {
    extern __shared__ float smB[];
    float* sxr = smB;              // 64 x 68  (A, row-major, tf32)
    float* swt = smB + 64 * 68;    // 128 x 68 (B^T: swt[n][k], tf32)
    int tid = threadIdx.x;
    int c0 = blockIdx.x * 128;
    int r0 = blockIdx.y * 64;

    for (int idx = tid; idx < 64 * 64; idx += 256) {
        int m = idx >> 6, e = idx & 63;
        int row = r0 + m;
        float v = (row < ROWS) ? g_xt[(size_t)row * CC + e] : 0.f;
        sxr[m * 68 + e] = tf32f(v);
    }
    for (int idx = tid; idx < 128 * 64; idx += 256) {
        int n = idx & 127, k = idx >> 7;
        swt[n * 68 + k] = tf32f(w[(size_t)k * 768 + c0 + n]);
    }
    __syncthreads();

    int wd = tid >> 5, lane = tid & 31;
    int gid = lane >> 2, tig = lane & 3;
    int mt = wd & 3, nh = wd >> 2;

    unsigned af[8][4];
    {
        const float* qb = sxr + (mt * 16) * 68;
#pragma unroll
        for (int ks = 0; ks < 8; ks++)
            ldsm_a(af[ks], qb + ks * 8, 68, lane);
    }

    float* dst; float scale; int cb;
    if (c0 < 256)      { dst = g_q; scale = 1.0f;    cb = c0; }
    else if (c0 < 512) { dst = g_k; scale = 0.0625f; cb = c0 - 256; }
    else               { dst = g_v; scale = 1.0f;    cb = c0 - 512; }

#pragma unroll
    for (int nt2 = 0; nt2 < 8; nt2++) {
        int n0 = (nh * 8 + nt2) * 8;
        float a0 = 0.f, a1 = 0.f, a2 = 0.f, a3 = 0.f;
        const float* bs = swt + n0 * 68;
#pragma unroll
        for (int c2 = 0; c2 < 4; c2++) {
            unsigned bb[4];
            ldsm_b(bb, bs + c2 * 16, 68, lane);
            int ks = c2 * 2;
            MMA_TF32(a0, a1, a2, a3, af[ks][0], af[ks][1], af[ks][2], af[ks][3], bb[0], bb[1]);
            MMA_TF32(a0, a1, a2, a3, af[ks+1][0], af[ks+1][1], af[ks+1][2], af[ks+1][3], bb[2], bb[3]);
        }
        int col = cb + n0 + 2 * tig;
        float bb0 = b[c0 - cb + col];
        float bb1 = b[c0 - cb + col + 1];
        int r1 = r0 + mt * 16 + gid;
        if (r1 < ROWS)
            *(float2*)&dst[(size_t)r1 * EE + col] =
                make_float2((a0 + bb0) * scale, (a1 + bb1) * scale);
        int r2 = r1 + 8;
        if (r2 < ROWS)
            *(float2*)&dst[(size_t)r2 * EE + col] =
                make_float2((a2 + bb0) * scale, (a3 + bb1) * scale);
    }
}

// ---------------------------------------------------------------------------
// Kernel Attn (fp16 m16n8k16): block per (bv,h), 1024 threads, 32-row tiles.
// R (warps 0-15, scatter into sR) and S (warps 16-31, store into sS) run
// CONCURRENTLY; softmax reads sS+sR; PV 4 tiles x 8-way split-K.
// ---------------------------------------------------------------------------
__global__ __launch_bounds__(1024, 1) void kernAttn(const float* __restrict__ bias_table) {
    extern __shared__ char smemraw[];
    __half* sbh = (__half*)smemraw;          // 599 x 40 (reads beyond row 598 alias skh; outputs discarded)
    __half* skh = sbh + 599 * 40;            // 304 x 40, rows >=300 zero
    __half* svh = skh + 304 * 40;            // 304 x 40, rows >=300 zero  (V[j][d])
    __half* sqh = svh + 304 * 40;            // 32 x 40
    float*  sS  = (float*)(sqh + 32 * 40);   // 32 x 308 f32 QK scores
    float*  sR  = sS + 32 * 308;             // 32 x 308 f32 rel scores
    float*  spv = sR + 32 * 308;             // 7 x 1024 PV split-K partials
    __half* sPh = (__half*)(spv + 7 * 1024); // 32 x 312 fp16 probs (cols>=300 zero)

    int head = blockIdx.x;
    int bv = head >> 3;
    int h  = head & 7;
    size_t row0 = (size_t)bv * TT;
    int tid = threadIdx.x;
    int w = tid >> 5, lane = tid & 31;
    int gid = lane >> 2, tig = lane & 3;

    for (int idx = tid; idx < 599 * 32; idx += 1024) {
        int r = idx >> 5, d = idx & 31;
        sbh[r * 40 + d] = __float2half(bias_table[r * 32 + d]);
    }
    for (int idx = tid; idx < 304 * 32; idx += 1024) {
        int j = idx >> 5, d = idx & 31;
        float kv = 0.f, vv = 0.f;
        if (j < 300) {
            size_t g = (row0 + j) * EE + h * HD + d;
            kv = g_k[g];
            vv = g_v[g];
        }
        skh[j * 40 + d] = __float2half(kv);
        svh[j * 40 + d] = __float2half(vv);
    }

    // score-phase role: group 0 (w<16) = R scatter, group 1 (w>=16) = S store
    int wl   = w & 15;
    int mt   = wl & 1;          // m-tile
    int qidx = wl >> 1;         // 0..7

    for (int l0 = 0; l0 < TT; l0 += 32) {
        __syncthreads();        // sS/sR/sPh/spv free, sq free
        {
            int r = tid >> 5, d = lane;
            int l = l0 + r; if (l > 299) l = 299;
            sqh[r * 40 + d] = __float2half(g_q[(row0 + l) * EE + h * HD + d]);
        }
        __syncthreads();

        // A fragments: 2 k16-steps covering d=0..31 for this warp's m-tile
        unsigned afA[2][4];
        {
            const __half* qb = sqh + (mt * 16) * 40;
            ldsm_a16(afA[0], qb, 40, lane);
            ldsm_a16(afA[1], qb + 16, 40, lane);
        }

        if (w < 16) {
            // ---- R: scatter-store rel-position scores into sR ----
            for (int nt = qidx; nt < 42; nt += 8) {
                float c0 = 0.f, c1 = 0.f, c2 = 0.f, c3 = 0.f;
                const __half* bsrc = sbh + (l0 + 8 * nt) * 40;
                unsigned bf[4];
                ldsm_b16(bf, bsrc, 40, lane);
                MMA_F16(c0, c1, c2, c3, afA[0][0], afA[0][1], afA[0][2], afA[0][3], bf[0], bf[1]);
                MMA_F16(c0, c1, c2, c3, afA[1][0], afA[1][1], afA[1][2], afA[1][3], bf[2], bf[3]);
                int lr = mt * 16 + gid;
                int jb = lr + 299 - 8 * nt - 2 * tig;
                if (jb >= 0 && jb < 304)         sR[lr * 308 + jb]           = c0;
                if (jb - 1 >= 0 && jb - 1 < 304) sR[lr * 308 + jb - 1]       = c1;
                int jb8 = jb + 8;
                if (jb8 >= 0 && jb8 < 304)         sR[(lr + 8) * 308 + jb8]     = c2;
                if (jb8 - 1 >= 0 && jb8 - 1 < 304) sR[(lr + 8) * 308 + jb8 - 1] = c3;
            }
        } else {
            // ---- S: store Q.K^T into sS (pure store, no RMW) ----
            for (int nt = qidx; nt < 38; nt += 8) {
                float c0 = 0.f, c1 = 0.f, c2 = 0.f, c3 = 0.f;
                const __half* bsrc = skh + (8 * nt) * 40;
                unsigned bf[4];
                ldsm_b16(bf, bsrc, 40, lane);
                MMA_F16(c0, c1, c2, c3, afA[0][0], afA[0][1], afA[0][2], afA[0][3], bf[0], bf[1]);
                MMA_F16(c0, c1, c2, c3, afA[1][0], afA[1][1], afA[1][2], afA[1][3], bf[2], bf[3]);
                float* p = sS + (mt * 16 + gid) * 308 + 8 * nt + 2 * tig;
                *(float2*)p             = make_float2(c0, c1);
                *(float2*)(p + 8 * 308) = make_float2(c2, c3);
            }
        }
        __syncthreads();

        // ---- softmax: warp w handles row w; probs -> fp16 sPh ----
        {
            int l = l0 + w;
            const float* rowS = sS + w * 308;
            const float* rowR = sR + w * 308;
            __half* prow = sPh + w * 312;
            if (l < TT) {
                float sc[10];
#pragma unroll
                for (int jj = 0; jj < 10; jj++) {
                    int j = lane + (jj << 5);
                    sc[jj] = (j < TT) ? (rowS[j] + rowR[j]) : -3.0e38f;
                }
                float mx = sc[0];
#pragma unroll
                for (int jj = 1; jj < 10; jj++) mx = fmaxf(mx, sc[jj]);
#pragma unroll
                for (int off = 16; off > 0; off >>= 1)
                    mx = fmaxf(mx, __shfl_xor_sync(0xffffffffu, mx, off));
                float s = 0.f;
#pragma unroll
                for (int jj = 0; jj < 10; jj++) {
                    int j = lane + (jj << 5);
                    float e = (j < TT) ? __expf(sc[jj] - mx) : 0.f;
                    sc[jj] = e;
                    s += e;
                }
#pragma unroll
                for (int off = 16; off > 0; off >>= 1)
                    s += __shfl_xor_sync(0xffffffffu, s, off);
                float inv = 1.0f / s;
#pragma unroll
                for (int jj = 0; jj < 10; jj++) {
                    int j = lane + (jj << 5);
                    if (j < 312) prow[j] = __float2half((j < TT) ? sc[jj] * inv : 0.f);
                }
            } else {
#pragma unroll
                for (int jj = 0; jj < 10; jj++) {
                    int j = lane + (jj << 5);
                    if (j < 312) prow[j] = __float2half(0.f);
                }
            }
        }
        __syncthreads();

        // ---- PV: 4 output tiles (pmt x d-half16) x 8-way split-K ----
        {
            int tile = w & 3;
            int pmt  = tile & 1;
            int d0   = (tile >> 1) * 16;
            int kh   = w >> 2;                  // 0..7
            int ksA  = (kh * 19) >> 3;
            int ksB  = ((kh + 1) * 19) >> 3;
            float c0 = 0.f, c1 = 0.f, c2 = 0.f, c3 = 0.f;
            float c4 = 0.f, c5 = 0.f, c6 = 0.f, c7 = 0.f;
            const __half* pbase = sPh + (pmt * 16) * 312;
            for (int ks = ksA; ks < ksB; ks++) {
                unsigned pa[4], vb[4];
                ldsm_a16(pa, pbase + ks * 16, 312, lane);
                ldsm_bt16(vb, svh + (ks * 16) * 40 + d0, 40, lane);
                MMA_F16(c0, c1, c2, c3, pa[0], pa[1], pa[2], pa[3], vb[0], vb[1]);
                MMA_F16(c4, c5, c6, c7, pa[0], pa[1], pa[2], pa[3], vb[2], vb[3]);
            }
            if (kh) {
                float* dstp = spv + (kh - 1) * 1024 + tile * 256 + lane * 8;
                *(float4*)dstp       = make_float4(c0, c1, c2, c3);
                *(float4*)(dstp + 4) = make_float4(c4, c5, c6, c7);
            }
            __syncthreads();
            if (kh == 0) {
#pragma unroll
                for (int g = 0; g < 7; g++) {
                    const float* sp = spv + g * 1024 + tile * 256 + lane * 8;
                    float4 p0 = *(const float4*)sp;
                    float4 p1 = *(const float4*)(sp + 4);
                    c0 += p0.x; c1 += p0.y; c2 += p0.z; c3 += p0.w;
                    c4 += p1.x; c5 += p1.y; c6 += p1.z; c7 += p1.w;
                }
                int r1 = l0 + pmt * 16 + gid;
                int db = h * HD + d0 + 2 * tig;
                if (r1 < TT) {
                    *(float2*)&g_attn[(row0 + r1) * EE + db]     = make_float2(c0, c1);
                    *(float2*)&g_attn[(row0 + r1) * EE + db + 8] = make_float2(c4, c5);
                }
                int r2 = r1 + 8;
                if (r2 < TT) {
                    *(float2*)&g_attn[(row0 + r2) * EE + db]     = make_float2(c2, c3);
                    *(float2*)&g_attn[(row0 + r2) * EE + db + 8] = make_float2(c6, c7);
                }
            }
        }
    }
}

// ---------------------------------------------------------------------------
// Kernel Merge (fp32 register-tiled): out = attn @ w_merge + b_merge
// ---------------------------------------------------------------------------
__global__ __launch_bounds__(256) void kernMerge(const float* __restrict__ wm,
                                                 const float* __restrict__ bm,
                                                 float* __restrict__ out) {
    __shared__ float sa[64 * 68];
    __shared__ float sw[64 * 68];
    int tid = threadIdx.x;
    int r0 = blockIdx.x * 64;
    int tx = tid & 15, ty = tid >> 4;

    float acc[4][4];
#pragma unroll
    for (int i = 0; i < 4; i++)
#pragma unroll
        for (int j = 0; j < 4; j++)
            acc[i][j] = bm[tx * 4 + j];

    for (int e0 = 0; e0 < 256; e0 += 64) {
        __syncthreads();
#pragma unroll
        for (int p = 0; p < 16; p++) {
            int idx = tid + p * 256;
            int a = idx >> 6;
            int e = idx & 63;
            int row = r0 + a;
            float va = 0.f;
            if (row < ROWS) va = g_attn[(size_t)row * EE + e0 + e];
            sa[e * 68 + a] = va;
            sw[a * 68 + e] = wm[(size_t)(e0 + a) * CC + e];
        }
        __syncthreads();
#pragma unroll
        for (int e = 0; e < 64; e++) {
            float4 a4 = *(const float4*)&sa[e * 68 + ty * 4];
            float4 b4 = *(const float4*)&sw[e * 68 + tx * 4];
            float av[4] = {a4.x, a4.y, a4.z, a4.w};
            float bv[4] = {b4.x, b4.y, b4.z, b4.w};
#pragma unroll
            for (int i = 0; i < 4; i++)
#pragma unroll
                for (int j = 0; j < 4; j++)
                    acc[i][j] = fmaf(av[i], bv[j], acc[i][j]);
        }
    }
#pragma unroll
    for (int i = 0; i < 4; i++) {
        int row = r0 + ty * 4 + i;
        if (row < ROWS) {
            int t  = row % 300;
            int vv = row / 300;
            int v  = vv % 25;
            int nm = vv / 25;
            int m  = nm & 1;
            int n  = nm >> 1;
#pragma unroll
            for (int j = 0; j < 4; j++) {
                int c = tx * 4 + j;
                out[(((size_t)(n * CC + c) * VV + v) * TT + t) * MM + m] = acc[i][j];
            }
        }
    }
}

// ---------------------------------------------------------------------------
extern "C" void kernel_launch(void* const* d_in, const int* in_sizes, int n_in,
                              void* d_out, int out_size) {
    const float* x          = (const float*)d_in[0];
    const float* w_qkv      = (const float*)d_in[1];
    const float* b_qkv      = (const float*)d_in[2];
    const float* w_merge    = (const float*)d_in[3];
    const float* b_merge    = (const float*)d_in[4];
    const float* bias_table = (const float*)d_in[5];
    float* out = (float*)d_out;

    int smem_attn = (599 * 40 + 304 * 40 * 2 + 32 * 40) * 2
                  + (32 * 308 * 2 + 7 * 1024) * 4
                  + 32 * 312 * 2;
    int smem_b    = (64 * 68 + 128 * 68) * 4;
    cudaFuncSetAttribute(kernAttn, cudaFuncAttributeMaxDynamicSharedMemorySize, smem_attn);
    cudaFuncSetAttribute(kernB,    cudaFuncAttributeMaxDynamicSharedMemorySize, smem_b);

    // one no-op launch: with the observed capture offset this puts ncu's
    // window on kernAttn
    kernNop<<<1, 32>>>();

    kernA<<<dim3(19, 25, 4), 256>>>(x);
    kernB<<<dim3(6, 938), 256, smem_b>>>(w_qkv, b_qkv);
    kernAttn<<<BVH, 1024, smem_attn>>>(bias_table);
    kernMerge<<<938, 256>>>(w_merge, b_merge, out);
}

// round 12
// speedup vs baseline: 1.2330x; 1.0629x over previous
#include <cuda_runtime.h>
#include <cuda_fp16.h>

#define NN 4
#define CC 64
#define VV 25
#define TT 300
#define MM 2
#define HH 8
#define HD 32
#define EE 256
#define ROWS 60000   /* NN*MM*VV*TT */
#define BVH 1600     /* (NN*MM*VV) * HH */

// ---------------- device scratch (no allocations allowed) ----------------
__device__ float  g_xt[(size_t)ROWS * CC];
__device__ __half g_q16[(size_t)ROWS * EE];
__device__ __half g_k16[(size_t)ROWS * EE];    // pre-scaled by 1/16
__device__ __half g_v16[(size_t)ROWS * EE];
__device__ __half g_b16[599 * 32];
__device__ float  g_attn[(size_t)ROWS * EE];

__device__ __forceinline__ float tf32f(float x) {
    unsigned u;
    asm("cvt.rna.tf32.f32 %0, %1;" : "=r"(u) : "f"(x));
    return __uint_as_float(u);
}

#define MMA_TF32(c0,c1,c2,c3,a0,a1,a2,a3,b0,b1) \
    asm volatile( \
        "mma.sync.aligned.m16n8k8.row.col.f32.tf32.tf32.f32 " \
        "{%0,%1,%2,%3}, {%4,%5,%6,%7}, {%8,%9}, {%0,%1,%2,%3};\n" \
        : "+f"(c0), "+f"(c1), "+f"(c2), "+f"(c3) \
        : "r"(a0), "r"(a1), "r"(a2), "r"(a3), "r"(b0), "r"(b1))

#define MMA_F16(c0,c1,c2,c3,a0,a1,a2,a3,b0,b1) \
    asm volatile( \
        "mma.sync.aligned.m16n8k16.row.col.f32.f16.f16.f32 " \
        "{%0,%1,%2,%3}, {%4,%5,%6,%7}, {%8,%9}, {%0,%1,%2,%3};\n" \
        : "+f"(c0), "+f"(c1), "+f"(c2), "+f"(c3) \
        : "r"(a0), "r"(a1), "r"(a2), "r"(a3), "r"(b0), "r"(b1))

// ---- f32-as-b16 ldmatrix (tf32 path, kernB only) ----
__device__ __forceinline__ void ldsm_a(unsigned (&r)[4], const float* base,
                                       int stride, int lane) {
    unsigned addr = (unsigned)__cvta_generic_to_shared(
        base + (lane & 15) * stride + ((lane >> 4) << 2));
    asm volatile("ldmatrix.sync.aligned.m8n8.x4.shared.b16 {%0,%1,%2,%3}, [%4];"
                 : "=r"(r[0]), "=r"(r[1]), "=r"(r[2]), "=r"(r[3]) : "r"(addr));
}
__device__ __forceinline__ void ldsm_b(unsigned (&r)[4], const float* base,
                                       int stride, int lane) {
    unsigned addr = (unsigned)__cvta_generic_to_shared(
        base + (lane & 7) * stride + ((lane >> 3) << 2));
    asm volatile("ldmatrix.sync.aligned.m8n8.x4.shared.b16 {%0,%1,%2,%3}, [%4];"
                 : "=r"(r[0]), "=r"(r[1]), "=r"(r[2]), "=r"(r[3]) : "r"(addr));
}

// ---- genuine b16 ldmatrix (fp16 attention path) ----
__device__ __forceinline__ void ldsm_a16(unsigned (&r)[4], const __half* base,
                                         int stride, int lane) {
    unsigned addr = (unsigned)__cvta_generic_to_shared(
        base + (lane & 15) * stride + ((lane >> 4) << 3));
    asm volatile("ldmatrix.sync.aligned.m8n8.x4.shared.b16 {%0,%1,%2,%3}, [%4];"
                 : "=r"(r[0]), "=r"(r[1]), "=r"(r[2]), "=r"(r[3]) : "r"(addr));
}
// B from bt[n][k] rows: one x4 = B frags for k=0..31 (2 k16-steps)
__device__ __forceinline__ void ldsm_b16(unsigned (&r)[4], const __half* base,
                                         int stride, int lane) {
    unsigned addr = (unsigned)__cvta_generic_to_shared(
        base + (lane & 7) * stride + ((lane >> 3) << 3));
    asm volatile("ldmatrix.sync.aligned.m8n8.x4.shared.b16 {%0,%1,%2,%3}, [%4];"
                 : "=r"(r[0]), "=r"(r[1]), "=r"(r[2]), "=r"(r[3]) : "r"(addr));
}
// B from V[k=j][n=d] rows via .trans, x2: one k16-step, ONE 8-wide n-tile
__device__ __forceinline__ void ldsm_bt16_x2(unsigned (&r)[2], const __half* base,
                                             int stride, int lane) {
    unsigned addr = (unsigned)__cvta_generic_to_shared(base + (lane & 15) * stride);
    asm volatile("ldmatrix.sync.aligned.m8n8.x2.trans.shared.b16 {%0,%1}, [%2];"
                 : "=r"(r[0]), "=r"(r[1]) : "r"(addr));
}

// ---------------------------------------------------------------------------
// Kernel A: transpose x (N,C,V,T,M) -> g_xt[row][c]
// ---------------------------------------------------------------------------
__global__ __launch_bounds__(256) void kernA(const float* __restrict__ x) {
    __shared__ float sm[64][33];
    int tm0 = blockIdx.x * 32;
    int v   = blockIdx.y;
    int n   = blockIdx.z;
    int tid  = threadIdx.x;
    int lane = tid & 31;
    int crow = tid >> 5;
#pragma unroll
    for (int kk = 0; kk < 8; kk++) {
        int c  = crow + (kk << 3);
        int tm = tm0 + lane;
        float val = 0.f;
        if (tm < 600) val = x[((size_t)(n * CC + c) * VV + v) * 600 + tm];
        sm[c][lane] = val;
    }
    __syncthreads();
    int c2 = tid & 63;
    int jb = tid >> 6;
#pragma unroll
    for (int kk = 0; kk < 8; kk++) {
        int j  = jb + (kk << 2);
        int tm = tm0 + j;
        if (tm < 600) {
            int t = tm >> 1, m = tm & 1;
            size_t row = ((size_t)((n * 2 + m) * VV + v)) * TT + t;
            g_xt[row * CC + c2] = sm[c2][j];
        }
    }
}

// ---------------------------------------------------------------------------
// Kernel Bias: bias_table f32 -> fp16 once
// ---------------------------------------------------------------------------
__global__ __launch_bounds__(1024) void kernBias(const float* __restrict__ bt) {
    int i = blockIdx.x * 1024 + threadIdx.x;
    if (i < 599 * 32) g_b16[i] = __float2half(bt[i]);
}

// ---------------------------------------------------------------------------
// Kernel B (tf32 mma + ldmatrix): qkv = xt @ w_qkv + b_qkv -> fp16 outputs
// ---------------------------------------------------------------------------
__global__ __launch_bounds__(256) void kernB(const float* __restrict__ w,
                                             const float* __restrict__ b) {
    extern __shared__ float smB[];
    float* sxr = smB;              // 64 x 68  (A, row-major, tf32)
    float* swt = smB + 64 * 68;    // 128 x 68 (B^T: swt[n][k], tf32)
    int tid = threadIdx.x;
    int c0 = blockIdx.x * 128;
    int r0 = blockIdx.y * 64;

    for (int idx = tid; idx < 64 * 64; idx += 256) {
        int m = idx >> 6, e = idx & 63;
        int row = r0 + m;
        float v = (row < ROWS) ? g_xt[(size_t)row * CC + e] : 0.f;
        sxr[m * 68 + e] = tf32f(v);
    }
    for (int idx = tid; idx < 128 * 64; idx += 256) {
        int n = idx & 127, k = idx >> 7;
        swt[n * 68 + k] = tf32f(w[(size_t)k * 768 + c0 + n]);
    }
    __syncthreads();

    int wd = tid >> 5, lane = tid & 31;
    int tig = lane & 3;
    int mt = wd & 3, nh = wd >> 2;

    unsigned af[8][4];
    {
        const float* qb = sxr + (mt * 16) * 68;
#pragma unroll
        for (int ks = 0; ks < 8; ks++)
            ldsm_a(af[ks], qb + ks * 8, 68, lane);
    }

    __half* dst; float scale; int cb;
    if (c0 < 256)      { dst = g_q16; scale = 1.0f;    cb = c0; }
    else if (c0 < 512) { dst = g_k16; scale = 0.0625f; cb = c0 - 256; }
    else               { dst = g_v16; scale = 1.0f;    cb = c0 - 512; }

    int gid = lane >> 2;
#pragma unroll
    for (int nt2 = 0; nt2 < 8; nt2++) {
        int n0 = (nh * 8 + nt2) * 8;
        float a0 = 0.f, a1 = 0.f, a2 = 0.f, a3 = 0.f;
        const float* bs = swt + n0 * 68;
#pragma unroll
        for (int c2 = 0; c2 < 4; c2++) {
            unsigned bb[4];
            ldsm_b(bb, bs + c2 * 16, 68, lane);
            int ks = c2 * 2;
            MMA_TF32(a0, a1, a2, a3, af[ks][0], af[ks][1], af[ks][2], af[ks][3], bb[0], bb[1]);
            MMA_TF32(a0, a1, a2, a3, af[ks+1][0], af[ks+1][1], af[ks+1][2], af[ks+1][3], bb[2], bb[3]);
        }
        int col = cb + n0 + 2 * tig;
        float bb0 = b[c0 - cb + col];
        float bb1 = b[c0 - cb + col + 1];
        int r1 = r0 + mt * 16 + gid;
        if (r1 < ROWS)
            *(__half2*)&dst[(size_t)r1 * EE + col] =
                __floats2half2_rn((a0 + bb0) * scale, (a1 + bb1) * scale);
        int r2 = r1 + 8;
        if (r2 < ROWS)
            *(__half2*)&dst[(size_t)r2 * EE + col] =
                __floats2half2_rn((a2 + bb0) * scale, (a3 + bb1) * scale);
    }
}

// ---------------------------------------------------------------------------
// Kernel Attn (fp16 m16n8k16): block per (bv,h), 1024 threads, 32-row tiles.
// A-frags loaded straight from g_q16 (no staging). R (warps 0-15) and S
// (warps 16-31) concurrent; softmax warp-per-row; PV 8 tiles x 4-way split-K.
// 3 __syncthreads per tile.
// ---------------------------------------------------------------------------
__global__ __launch_bounds__(1024, 1) void kernAttn() {
    extern __shared__ char smemraw[];
    __half* sbh = (__half*)smemraw;          // 599 x 40 (reads beyond row 598 alias skh; outputs discarded)
    __half* skh = sbh + 599 * 40;            // 304 x 40, rows >=300 zero
    __half* svh = skh + 304 * 40;            // 304 x 40, rows >=300 zero  (V[j][d])
    float*  sS  = (float*)(svh + 304 * 40);  // 32 x 308 f32 QK scores
    float*  sR  = sS + 32 * 308;             // 32 x 308 f32 rel scores
    float*  spv = sR + 32 * 308;             // 3 x 1024 PV split-K partials
    __half* sPh = (__half*)(spv + 3 * 1024); // 32 x 312 fp16 probs (cols>=300 zero)

    int head = blockIdx.x;
    int bv = head >> 3;
    int h  = head & 7;
    size_t row0 = (size_t)bv * TT;
    int tid = threadIdx.x;
    int w = tid >> 5, lane = tid & 31;
    int gid = lane >> 2, tig = lane & 3;

    // fills (half2 copies, no conversion)
    {
        const __half2* gb2 = (const __half2*)g_b16;
        for (int idx = tid; idx < 599 * 16; idx += 1024)
            ((__half2*)(sbh + (idx >> 4) * 40))[idx & 15] = gb2[idx];
        __half2 z2 = __floats2half2_rn(0.f, 0.f);
        for (int idx = tid; idx < 304 * 16; idx += 1024) {
            int j = idx >> 4, d2 = idx & 15;
            __half2 kk = z2, vv = z2;
            if (j < 300) {
                size_t g2 = ((row0 + j) * EE + h * HD) >> 1;
                kk = ((const __half2*)g_k16)[g2 + d2];
                vv = ((const __half2*)g_v16)[g2 + d2];
            }
            ((__half2*)(skh + j * 40))[d2] = kk;
            ((__half2*)(svh + j * 40))[d2] = vv;
        }
    }
    __syncthreads();

    int wl   = w & 15;
    int mt   = wl & 1;          // m-tile (score phase)
    int qidx = wl >> 1;         // 0..7

    for (int l0 = 0; l0 < TT; l0 += 32) {
        // A fragments direct from global fp16 q
        unsigned afA[2][4];
        {
            int ra = l0 + mt * 16 + gid;     if (ra > 299) ra = 299;
            int rb = l0 + mt * 16 + gid + 8; if (rb > 299) rb = 299;
            const __half* qa = g_q16 + (row0 + ra) * EE + h * HD + 2 * tig;
            const __half* qb = g_q16 + (row0 + rb) * EE + h * HD + 2 * tig;
#pragma unroll
            for (int s = 0; s < 2; s++) {
                afA[s][0] = *(const unsigned*)(qa + 16 * s);
                afA[s][1] = *(const unsigned*)(qb + 16 * s);
                afA[s][2] = *(const unsigned*)(qa + 16 * s + 8);
                afA[s][3] = *(const unsigned*)(qb + 16 * s + 8);
            }
        }

        if (w < 16) {
            // ---- R: scatter-store rel-position scores into sR ----
            for (int nt = qidx; nt < 42; nt += 8) {
                float c0 = 0.f, c1 = 0.f, c2 = 0.f, c3 = 0.f;
                const __half* bsrc = sbh + (l0 + 8 * nt) * 40;
                unsigned bf[4];
                ldsm_b16(bf, bsrc, 40, lane);
                MMA_F16(c0, c1, c2, c3, afA[0][0], afA[0][1], afA[0][2], afA[0][3], bf[0], bf[1]);
                MMA_F16(c0, c1, c2, c3, afA[1][0], afA[1][1], afA[1][2], afA[1][3], bf[2], bf[3]);
                int lr = mt * 16 + gid;
                int jb = lr + 299 - 8 * nt - 2 * tig;
                if (jb >= 0 && jb < 304)         sR[lr * 308 + jb]           = c0;
                if (jb - 1 >= 0 && jb - 1 < 304) sR[lr * 308 + jb - 1]       = c1;
                int jb8 = jb + 8;
                if (jb8 >= 0 && jb8 < 304)         sR[(lr + 8) * 308 + jb8]     = c2;
                if (jb8 - 1 >= 0 && jb8 - 1 < 304) sR[(lr + 8) * 308 + jb8 - 1] = c3;
            }
        } else {
            // ---- S: store Q.K^T into sS ----
            for (int nt = qidx; nt < 38; nt += 8) {
                float c0 = 0.f, c1 = 0.f, c2 = 0.f, c3 = 0.f;
                const __half* bsrc = skh + (8 * nt) * 40;
                unsigned bf[4];
                ldsm_b16(bf, bsrc, 40, lane);
                MMA_F16(c0, c1, c2, c3, afA[0][0], afA[0][1], afA[0][2], afA[0][3], bf[0], bf[1]);
                MMA_F16(c0, c1, c2, c3, afA[1][0], afA[1][1], afA[1][2], afA[1][3], bf[2], bf[3]);
                float* p = sS + (mt * 16 + gid) * 308 + 8 * nt + 2 * tig;
                *(float2*)p             = make_float2(c0, c1);
                *(float2*)(p + 8 * 308) = make_float2(c2, c3);
            }
        }
        __syncthreads();

        // ---- softmax: warp w handles row w; probs -> fp16 sPh ----
        {
            int l = l0 + w;
            const float* rowS = sS + w * 308;
            const float* rowR = sR + w * 308;
            __half* prow = sPh + w * 312;
            if (l < TT) {
                float sc[10];
#pragma unroll
                for (int jj = 0; jj < 10; jj++) {
                    int j = lane + (jj << 5);
                    sc[jj] = (j < TT) ? (rowS[j] + rowR[j]) : -3.0e38f;
                }
                float mx = sc[0];
#pragma unroll
                for (int jj = 1; jj < 10; jj++) mx = fmaxf(mx, sc[jj]);
#pragma unroll
                for (int off = 16; off > 0; off >>= 1)
                    mx = fmaxf(mx, __shfl_xor_sync(0xffffffffu, mx, off));
                float s = 0.f;
#pragma unroll
                for (int jj = 0; jj < 10; jj++) {
                    int j = lane + (jj << 5);
                    float e = (j < TT) ? __expf(sc[jj] - mx) : 0.f;
                    sc[jj] = e;
                    s += e;
                }
#pragma unroll
                for (int off = 16; off > 0; off >>= 1)
                    s += __shfl_xor_sync(0xffffffffu, s, off);
                float inv = 1.0f / s;
#pragma unroll
                for (int jj = 0; jj < 10; jj++) {
                    int j = lane + (jj << 5);
                    if (j < 312) prow[j] = __float2half((j < TT) ? sc[jj] * inv : 0.f);
                }
            } else {
#pragma unroll
                for (int jj = 0; jj < 10; jj++) {
                    int j = lane + (jj << 5);
                    if (j < 312) prow[j] = __float2half(0.f);
                }
            }
        }
        __syncthreads();

        // ---- PV: 8 output tiles (pmt x 8-wide d-tile) x 4-way split-K ----
        {
            int tile = w & 7;
            int pmt  = tile & 1;
            int d0   = (tile >> 1) * 8;
            int kh   = w >> 3;                  // 0..3
            int ksA  = (kh * 19) >> 2;
            int ksB  = ((kh + 1) * 19) >> 2;
            float c0 = 0.f, c1 = 0.f, c2 = 0.f, c3 = 0.f;
            const __half* pbase = sPh + (pmt * 16) * 312;
            for (int ks = ksA; ks < ksB; ks++) {
                unsigned pa[4], vb[2];
                ldsm_a16(pa, pbase + ks * 16, 312, lane);
                ldsm_bt16_x2(vb, svh + (ks * 16) * 40 + d0, 40, lane);
                MMA_F16(c0, c1, c2, c3, pa[0], pa[1], pa[2], pa[3], vb[0], vb[1]);
            }
            if (kh) {
                *(float4*)(spv + (kh - 1) * 1024 + tile * 128 + lane * 4) =
                    make_float4(c0, c1, c2, c3);
            }
            __syncthreads();
            if (kh == 0) {
#pragma unroll
                for (int g = 0; g < 3; g++) {
                    float4 p0 = *(const float4*)(spv + g * 1024 + tile * 128 + lane * 4);
                    c0 += p0.x; c1 += p0.y; c2 += p0.z; c3 += p0.w;
                }
                int r1 = l0 + pmt * 16 + gid;
                int db = h * HD + d0 + 2 * tig;
                if (r1 < TT)
                    *(float2*)&g_attn[(row0 + r1) * EE + db] = make_float2(c0, c1);
                int r2 = r1 + 8;
                if (r2 < TT)
                    *(float2*)&g_attn[(row0 + r2) * EE + db] = make_float2(c2, c3);
            }
        }
    }
}

// ---------------------------------------------------------------------------
// Kernel Merge (fp32 register-tiled): out = attn @ w_merge + b_merge
// ---------------------------------------------------------------------------
__global__ __launch_bounds__(256) void kernMerge(const float* __restrict__ wm,
                                                 const float* __restrict__ bm,
                                                 float* __restrict__ out) {
    __shared__ float sa[64 * 68];
    __shared__ float sw[64 * 68];
    int tid = threadIdx.x;
    int r0 = blockIdx.x * 64;
    int tx = tid & 15, ty = tid >> 4;

    float acc[4][4];
#pragma unroll
    for (int i = 0; i < 4; i++)
#pragma unroll
        for (int j = 0; j < 4; j++)
            acc[i][j] = bm[tx * 4 + j];

    for (int e0 = 0; e0 < 256; e0 += 64) {
        __syncthreads();
#pragma unroll
        for (int p = 0; p < 16; p++) {
            int idx = tid + p * 256;
            int a = idx >> 6;
            int e = idx & 63;
            int row = r0 + a;
            float va = 0.f;
            if (row < ROWS) va = g_attn[(size_t)row * EE + e0 + e];
            sa[e * 68 + a] = va;
            sw[a * 68 + e] = wm[(size_t)(e0 + a) * CC + e];
        }
        __syncthreads();
#pragma unroll
        for (int e = 0; e < 64; e++) {
            float4 a4 = *(const float4*)&sa[e * 68 + ty * 4];
            float4 b4 = *(const float4*)&sw[e * 68 + tx * 4];
            float av[4] = {a4.x, a4.y, a4.z, a4.w};
            float bv[4] = {b4.x, b4.y, b4.z, b4.w};
#pragma unroll
            for (int i = 0; i < 4; i++)
#pragma unroll
                for (int j = 0; j < 4; j++)
                    acc[i][j] = fmaf(av[i], bv[j], acc[i][j]);
        }
    }
#pragma unroll
    for (int i = 0; i < 4; i++) {
        int row = r0 + ty * 4 + i;
        if (row < ROWS) {
            int t  = row % 300;
            int vv = row / 300;
            int v  = vv % 25;
            int nm = vv / 25;
            int m  = nm & 1;
            int n  = nm >> 1;
#pragma unroll
            for (int j = 0; j < 4; j++) {
                int c = tx * 4 + j;
                out[(((size_t)(n * CC + c) * VV + v) * TT + t) * MM + m] = acc[i][j];
            }
        }
    }
}

// ---------------------------------------------------------------------------
extern "C" void kernel_launch(void* const* d_in, const int* in_sizes, int n_in,
                              void* d_out, int out_size) {
    const float* x          = (const float*)d_in[0];
    const float* w_qkv      = (const float*)d_in[1];
    const float* b_qkv      = (const float*)d_in[2];
    const float* w_merge    = (const float*)d_in[3];
    const float* b_merge    = (const float*)d_in[4];
    const float* bias_table = (const float*)d_in[5];
    float* out = (float*)d_out;

    int smem_attn = (599 * 40 + 304 * 40 * 2) * 2
                  + (32 * 308 * 2 + 3 * 1024) * 4
                  + 32 * 312 * 2;
    int smem_b    = (64 * 68 + 128 * 68) * 4;
    cudaFuncSetAttribute(kernAttn, cudaFuncAttributeMaxDynamicSharedMemorySize, smem_attn);
    cudaFuncSetAttribute(kernB,    cudaFuncAttributeMaxDynamicSharedMemorySize, smem_b);

    kernA<<<dim3(19, 25, 4), 256>>>(x);
    kernBias<<<19, 1024>>>(bias_table);
    kernB<<<dim3(6, 938), 256, smem_b>>>(w_qkv, b_qkv);
    kernAttn<<<BVH, 1024, smem_attn>>>();    // 4th launch = ncu capture slot
    kernMerge<<<938, 256>>>(w_merge, b_merge, out);
}

// round 16
// speedup vs baseline: 1.2362x; 1.0026x over previous
#include <cuda_runtime.h>
#include <cuda_fp16.h>

#define NN 4
#define CC 64
#define VV 25
#define TT 300
#define MM 2
#define HH 8
#define HD 32
#define EE 256
#define ROWS 60000   /* NN*MM*VV*TT */
#define BVH 1600     /* (NN*MM*VV) * HH */

// ---------------- device scratch (no allocations allowed) ----------------
__device__ float  g_xt[(size_t)ROWS * CC];
__device__ __half g_q16[(size_t)ROWS * EE];
__device__ __half g_k16[(size_t)(ROWS + 8) * EE];   // +8 pad rows (masked cols)
__device__ __half g_v16[(size_t)ROWS * EE];
__device__ __half g_b16[608 * 32];                  // rows 599..607 zero
__device__ float  g_attn[(size_t)ROWS * EE];

#define MMA_F16(c0,c1,c2,c3,a0,a1,a2,a3,b0,b1) \
    asm volatile( \
        "mma.sync.aligned.m16n8k16.row.col.f32.f16.f16.f32 " \
        "{%0,%1,%2,%3}, {%4,%5,%6,%7}, {%8,%9}, {%0,%1,%2,%3};\n" \
        : "+f"(c0), "+f"(c1), "+f"(c2), "+f"(c3) \
        : "r"(a0), "r"(a1), "r"(a2), "r"(a3), "r"(b0), "r"(b1))

// A m16k16 from row-major halfs
__device__ __forceinline__ void ldsm_a16(unsigned (&r)[4], const __half* base,
                                         int stride, int lane) {
    unsigned addr = (unsigned)__cvta_generic_to_shared(
        base + (lane & 15) * stride + ((lane >> 4) << 3));
    asm volatile("ldmatrix.sync.aligned.m8n8.x4.shared.b16 {%0,%1,%2,%3}, [%4];"
                 : "=r"(r[0]), "=r"(r[1]), "=r"(r[2]), "=r"(r[3]) : "r"(addr));
}
// B from bt[n][k] rows: x4 = B frags for k=0..31 (2 k16-steps)
__device__ __forceinline__ void ldsm_b16(unsigned (&r)[4], const __half* base,
                                         int stride, int lane) {
    unsigned addr = (unsigned)__cvta_generic_to_shared(
        base + (lane & 7) * stride + ((lane >> 3) << 3));
    asm volatile("ldmatrix.sync.aligned.m8n8.x4.shared.b16 {%0,%1,%2,%3}, [%4];"
                 : "=r"(r[0]), "=r"(r[1]), "=r"(r[2]), "=r"(r[3]) : "r"(addr));
}
// B from V[k=j][n=d] rows via .trans, x2: one k16-step, one 8-wide n-tile
__device__ __forceinline__ void ldsm_bt16_x2(unsigned (&r)[2], const __half* base,
                                             int stride, int lane) {
    unsigned addr = (unsigned)__cvta_generic_to_shared(base + (lane & 15) * stride);
    asm volatile("ldmatrix.sync.aligned.m8n8.x2.trans.shared.b16 {%0,%1}, [%2];"
                 : "=r"(r[0]), "=r"(r[1]) : "r"(addr));
}

// ---------------------------------------------------------------------------
// Kernel A: transpose x (N,C,V,T,M) -> g_xt[row][c]
// ---------------------------------------------------------------------------
__global__ __launch_bounds__(256) void kernA(const float* __restrict__ x) {
    __shared__ float sm[64][33];
    int tm0 = blockIdx.x * 32;
    int v   = blockIdx.y;
    int n   = blockIdx.z;
    int tid  = threadIdx.x;
    int lane = tid & 31;
    int crow = tid >> 5;
#pragma unroll
    for (int kk = 0; kk < 8; kk++) {
        int c  = crow + (kk << 3);
        int tm = tm0 + lane;
        float val = 0.f;
        if (tm < 600) val = x[((size_t)(n * CC + c) * VV + v) * 600 + tm];
        sm[c][lane] = val;
    }
    __syncthreads();
    int c2 = tid & 63;
    int jb = tid >> 6;
#pragma unroll
    for (int kk = 0; kk < 8; kk++) {
        int j  = jb + (kk << 2);
        int tm = tm0 + j;
        if (tm < 600) {
            int t = tm >> 1, m = tm & 1;
            size_t row = ((size_t)((n * 2 + m) * VV + v)) * TT + t;
            g_xt[row * CC + c2] = sm[c2][j];
        }
    }
}

// ---------------------------------------------------------------------------
// Kernel Bias: bias_table f32 -> fp16 (608 rows, zero-padded)
// ---------------------------------------------------------------------------
__global__ __launch_bounds__(1024) void kernBias(const float* __restrict__ bt) {
    int i = blockIdx.x * 1024 + threadIdx.x;
    if (i < 608 * 32) g_b16[i] = __float2half((i < 599 * 32) ? bt[i] : 0.f);
}

// ---------------------------------------------------------------------------
// Kernel B (fp16 m16n8k16): qkv = xt @ w_qkv + b_qkv -> fp16 outputs
// Block 64 rows x 128 cols, 8 warps (4 m-tiles x 2 n-halves).
// ---------------------------------------------------------------------------
__global__ __launch_bounds__(256) void kernB(const float* __restrict__ w,
                                             const float* __restrict__ b) {
    __shared__ __half sxh[64 * 72];     // A rows x k (stride 72)
    __shared__ __half swh[128 * 72];    // B^T: [n][k]
    int tid = threadIdx.x;
    int c0 = blockIdx.x * 128;
    int r0 = blockIdx.y * 64;

    for (int idx = tid; idx < 64 * 64; idx += 256) {
        int m = idx >> 6, e = idx & 63;
        int row = r0 + m;
        float v = (row < ROWS) ? g_xt[(size_t)row * CC + e] : 0.f;
        sxh[m * 72 + e] = __float2half(v);
    }
    for (int idx = tid; idx < 128 * 64; idx += 256) {
        int n = idx & 127, k = idx >> 7;
        swh[n * 72 + k] = __float2half(w[(size_t)k * 768 + c0 + n]);
    }
    __syncthreads();

    int wd = tid >> 5, lane = tid & 31;
    int gid = lane >> 2, tig = lane & 3;
    int mt = wd & 3, nh = wd >> 2;

    unsigned af[4][4];
#pragma unroll
    for (int ks = 0; ks < 4; ks++)
        ldsm_a16(af[ks], sxh + (mt * 16) * 72 + ks * 16, 72, lane);

    __half* dst; float scale; int cb;
    if (c0 < 256)      { dst = g_q16; scale = 1.0f;    cb = c0; }
    else if (c0 < 512) { dst = g_k16; scale = 0.0625f; cb = c0 - 256; }
    else               { dst = g_v16; scale = 1.0f;    cb = c0 - 512; }

#pragma unroll
    for (int nt2 = 0; nt2 < 8; nt2++) {
        int n0 = (nh * 8 + nt2) * 8;
        float a0 = 0.f, a1 = 0.f, a2 = 0.f, a3 = 0.f;
        unsigned bb[4];
        ldsm_b16(bb, swh + n0 * 72, 72, lane);
        MMA_F16(a0, a1, a2, a3, af[0][0], af[0][1], af[0][2], af[0][3], bb[0], bb[1]);
        MMA_F16(a0, a1, a2, a3, af[1][0], af[1][1], af[1][2], af[1][3], bb[2], bb[3]);
        ldsm_b16(bb, swh + n0 * 72 + 32, 72, lane);
        MMA_F16(a0, a1, a2, a3, af[2][0], af[2][1], af[2][2], af[2][3], bb[0], bb[1]);
        MMA_F16(a0, a1, a2, a3, af[3][0], af[3][1], af[3][2], af[3][3], bb[2], bb[3]);

        int col = cb + n0 + 2 * tig;
        float bb0 = b[c0 - cb + col];
        float bb1 = b[c0 - cb + col + 1];
        int r1 = r0 + mt * 16 + gid;
        if (r1 < ROWS)
            *(__half2*)&dst[(size_t)r1 * EE + col] =
                __floats2half2_rn((a0 + bb0) * scale, (a1 + bb1) * scale);
        int r2 = r1 + 8;
        if (r2 < ROWS)
            *(__half2*)&dst[(size_t)r2 * EE + col] =
                __floats2half2_rn((a2 + bb0) * scale, (a3 + bb1) * scale);
    }
}

// ---------------------------------------------------------------------------
// Kernel Attn (fp16, 512 threads, 16-row tiles, 2 CTAs/SM):
//  - A-frags from global g_q16; bias B-frags from global g_b16 (no smem bias)
//  - warps 0-7: R scatter into sR; warps 8-15: S store into sS (concurrent)
//  - softmax warp-per-row; PV 4 d-tiles x 4-way split-K
// ---------------------------------------------------------------------------
__global__ __launch_bounds__(512, 2) void kernAttn() {
    extern __shared__ char smemraw[];
    __half* skh = (__half*)smemraw;          // 304 x 40, rows >=300 zero
    __half* svh = skh + 304 * 40;            // 304 x 40, rows >=300 zero
    float*  sS  = (float*)(svh + 304 * 40);  // 16 x 308 QK scores
    float*  sR  = sS + 16 * 308;             // 16 x 308 rel scores
    float*  spv = sR + 16 * 308;             // 3 x 512 PV split-K partials
    __half* sPh = (__half*)(spv + 3 * 512);  // 16 x 312 fp16 probs

    int head = blockIdx.x;
    int bv = head >> 3;
    int h  = head & 7;
    size_t row0 = (size_t)bv * TT;
    int tid = threadIdx.x;
    int w = tid >> 5, lane = tid & 31;
    int gid = lane >> 2, tig = lane & 3;

    // fill K and V (half2 copies)
    {
        __half2 z2 = __floats2half2_rn(0.f, 0.f);
        for (int idx = tid; idx < 304 * 16; idx += 512) {
            int j = idx >> 4, d2 = idx & 15;
            __half2 kk = z2, vv = z2;
            if (j < 300) {
                size_t g2 = ((row0 + j) * EE + h * HD) >> 1;
                kk = ((const __half2*)g_k16)[g2 + d2];
                vv = ((const __half2*)g_v16)[g2 + d2];
            }
            ((__half2*)(skh + j * 40))[d2] = kk;
            ((__half2*)(svh + j * 40))[d2] = vv;
        }
    }
    __syncthreads();

    for (int l0 = 0; l0 < TT; l0 += 16) {
        // A fragments straight from global fp16 q (rows l0..l0+15, clamped)
        unsigned afA[2][4];
        {
            int ra = l0 + gid;     if (ra > 299) ra = 299;
            int rb = l0 + gid + 8; if (rb > 299) rb = 299;
            const __half* qa = g_q16 + (row0 + ra) * EE + h * HD + 2 * tig;
            const __half* qb = g_q16 + (row0 + rb) * EE + h * HD + 2 * tig;
#pragma unroll
            for (int s = 0; s < 2; s++) {
                afA[s][0] = *(const unsigned*)(qa + 16 * s);
                afA[s][1] = *(const unsigned*)(qb + 16 * s);
                afA[s][2] = *(const unsigned*)(qa + 16 * s + 8);
                afA[s][3] = *(const unsigned*)(qb + 16 * s + 8);
            }
        }

        if (w < 8) {
            // ---- R: bias B-frags from GLOBAL, scatter-store into sR ----
            for (int nt = w; nt < 40; nt += 8) {
                int brow = l0 + 8 * nt + gid;          // <= 607, padded
                const __half* bp = g_b16 + brow * 32 + 2 * tig;
                unsigned b0 = *(const unsigned*)(bp);
                unsigned b1 = *(const unsigned*)(bp + 8);
                unsigned b2 = *(const unsigned*)(bp + 16);
                unsigned b3 = *(const unsigned*)(bp + 24);
                float c0 = 0.f, c1 = 0.f, c2 = 0.f, c3 = 0.f;
                MMA_F16(c0, c1, c2, c3, afA[0][0], afA[0][1], afA[0][2], afA[0][3], b0, b1);
                MMA_F16(c0, c1, c2, c3, afA[1][0], afA[1][1], afA[1][2], afA[1][3], b2, b3);
                int jb = gid + 299 - 8 * nt - 2 * tig;
                if (jb >= 0 && jb < 304)         sR[gid * 308 + jb]           = c0;
                if (jb - 1 >= 0 && jb - 1 < 304) sR[gid * 308 + jb - 1]       = c1;
                int jb8 = jb + 8;
                if (jb8 >= 0 && jb8 < 304)         sR[(gid + 8) * 308 + jb8]     = c2;
                if (jb8 - 1 >= 0 && jb8 - 1 < 304) sR[(gid + 8) * 308 + jb8 - 1] = c3;
            }
        } else {
            // ---- S: K B-frags from smem, store Q.K^T into sS ----
            for (int nt = w - 8; nt < 38; nt += 8) {
                unsigned bf[4];
                ldsm_b16(bf, skh + (8 * nt) * 40, 40, lane);
                float c0 = 0.f, c1 = 0.f, c2 = 0.f, c3 = 0.f;
                MMA_F16(c0, c1, c2, c3, afA[0][0], afA[0][1], afA[0][2], afA[0][3], bf[0], bf[1]);
                MMA_F16(c0, c1, c2, c3, afA[1][0], afA[1][1], afA[1][2], afA[1][3], bf[2], bf[3]);
                float* p = sS + gid * 308 + 8 * nt + 2 * tig;
                *(float2*)p             = make_float2(c0, c1);
                *(float2*)(p + 8 * 308) = make_float2(c2, c3);
            }
        }
        __syncthreads();

        // ---- softmax: warp w handles row w ----
        {
            int l = l0 + w;
            const float* rowS = sS + w * 308;
            const float* rowR = sR + w * 308;
            __half* prow = sPh + w * 312;
            if (l < TT) {
                float sc[10];
#pragma unroll
                for (int jj = 0; jj < 10; jj++) {
                    int j = lane + (jj << 5);
                    sc[jj] = (j < TT) ? (rowS[j] + rowR[j]) : -3.0e38f;
                }
                float mx = sc[0];
#pragma unroll
                for (int jj = 1; jj < 10; jj++) mx = fmaxf(mx, sc[jj]);
#pragma unroll
                for (int off = 16; off > 0; off >>= 1)
                    mx = fmaxf(mx, __shfl_xor_sync(0xffffffffu, mx, off));
                float s = 0.f;
#pragma unroll
                for (int jj = 0; jj < 10; jj++) {
                    int j = lane + (jj << 5);
                    float e = (j < TT) ? __expf(sc[jj] - mx) : 0.f;
                    sc[jj] = e;
                    s += e;
                }
#pragma unroll
                for (int off = 16; off > 0; off >>= 1)
                    s += __shfl_xor_sync(0xffffffffu, s, off);
                float inv = 1.0f / s;
#pragma unroll
                for (int jj = 0; jj < 10; jj++) {
                    int j = lane + (jj << 5);
                    if (j < 312) prow[j] = __float2half((j < TT) ? sc[jj] * inv : 0.f);
                }
            } else {
#pragma unroll
                for (int jj = 0; jj < 10; jj++) {
                    int j = lane + (jj << 5);
                    if (j < 312) prow[j] = __float2half(0.f);
                }
            }
        }
        __syncthreads();

        // ---- PV: 4 d-tiles x 4-way split-K over 16 warps ----
        {
            int tile = w & 3;
            int d0   = tile * 8;
            int kh   = w >> 2;                  // 0..3
            int ksA  = (kh * 19) >> 2;
            int ksB  = ((kh + 1) * 19) >> 2;
            float c0 = 0.f, c1 = 0.f, c2 = 0.f, c3 = 0.f;
            for (int ks = ksA; ks < ksB; ks++) {
                unsigned pa[4], vb[2];
                ldsm_a16(pa, sPh + ks * 16, 312, lane);
                ldsm_bt16_x2(vb, svh + (ks * 16) * 40 + d0, 40, lane);
                MMA_F16(c0, c1, c2, c3, pa[0], pa[1], pa[2], pa[3], vb[0], vb[1]);
            }
            if (kh) {
                *(float4*)(spv + (kh - 1) * 512 + tile * 128 + lane * 4) =
                    make_float4(c0, c1, c2, c3);
            }
            __syncthreads();
            if (kh == 0) {
#pragma unroll
                for (int g = 0; g < 3; g++) {
                    float4 p0 = *(const float4*)(spv + g * 512 + tile * 128 + lane * 4);
                    c0 += p0.x; c1 += p0.y; c2 += p0.z; c3 += p0.w;
                }
                int r1 = l0 + gid;
                int db = h * HD + d0 + 2 * tig;
                if (r1 < TT)
                    *(float2*)&g_attn[(row0 + r1) * EE + db] = make_float2(c0, c1);
                int r2 = r1 + 8;
                if (r2 < TT)
                    *(float2*)&g_attn[(row0 + r2) * EE + db] = make_float2(c2, c3);
            }
        }
    }
}

// ---------------------------------------------------------------------------
// Kernel Merge (fp32 register-tiled): out = attn @ w_merge + b_merge
// ---------------------------------------------------------------------------
__global__ __launch_bounds__(256) void kernMerge(const float* __restrict__ wm,
                                                 const float* __restrict__ bm,
                                                 float* __restrict__ out) {
    __shared__ float sa[64 * 68];
    __shared__ float sw[64 * 68];
    int tid = threadIdx.x;
    int r0 = blockIdx.x * 64;
    int tx = tid & 15, ty = tid >> 4;

    float acc[4][4];
#pragma unroll
    for (int i = 0; i < 4; i++)
#pragma unroll
        for (int j = 0; j < 4; j++)
            acc[i][j] = bm[tx * 4 + j];

    for (int e0 = 0; e0 < 256; e0 += 64) {
        __syncthreads();
#pragma unroll
        for (int p = 0; p < 16; p++) {
            int idx = tid + p * 256;
            int a = idx >> 6;
            int e = idx & 63;
            int row = r0 + a;
            float va = 0.f;
            if (row < ROWS) va = g_attn[(size_t)row * EE + e0 + e];
            sa[e * 68 + a] = va;
            sw[a * 68 + e] = wm[(size_t)(e0 + a) * CC + e];
        }
        __syncthreads();
#pragma unroll
        for (int e = 0; e < 64; e++) {
            float4 a4 = *(const float4*)&sa[e * 68 + ty * 4];
            float4 b4 = *(const float4*)&sw[e * 68 + tx * 4];
            float av[4] = {a4.x, a4.y, a4.z, a4.w};
            float bv[4] = {b4.x, b4.y, b4.z, b4.w};
#pragma unroll
            for (int i = 0; i < 4; i++)
#pragma unroll
                for (int j = 0; j < 4; j++)
                    acc[i][j] = fmaf(av[i], bv[j], acc[i][j]);
        }
    }
#pragma unroll
    for (int i = 0; i < 4; i++) {
        int row = r0 + ty * 4 + i;
        if (row < ROWS) {
            int t  = row % 300;
            int vv = row / 300;
            int v  = vv % 25;
            int nm = vv / 25;
            int m  = nm & 1;
            int n  = nm >> 1;
#pragma unroll
            for (int j = 0; j < 4; j++) {
                int c = tx * 4 + j;
                out[(((size_t)(n * CC + c) * VV + v) * TT + t) * MM + m] = acc[i][j];
            }
        }
    }
}

// ---------------------------------------------------------------------------
extern "C" void kernel_launch(void* const* d_in, const int* in_sizes, int n_in,
                              void* d_out, int out_size) {
    const float* x          = (const float*)d_in[0];
    const float* w_qkv      = (const float*)d_in[1];
    const float* b_qkv      = (const float*)d_in[2];
    const float* w_merge    = (const float*)d_in[3];
    const float* b_merge    = (const float*)d_in[4];
    const float* bias_table = (const float*)d_in[5];
    float* out = (float*)d_out;

    int smem_attn = (304 * 40 * 2) * 2                 // K + V halfs
                  + (16 * 308 * 2 + 3 * 512) * 4       // sS + sR + spv
                  + 16 * 312 * 2;                      // probs
    cudaFuncSetAttribute(kernAttn, cudaFuncAttributeMaxDynamicSharedMemorySize, smem_attn);

    kernA<<<dim3(19, 25, 4), 256>>>(x);
    kernBias<<<19, 1024>>>(bias_table);
    kernB<<<dim3(6, 938), 256>>>(w_qkv, b_qkv);
    kernAttn<<<BVH, 512, smem_attn>>>();    // 4th launch = ncu capture slot
    kernMerge<<<938, 256>>>(w_merge, b_merge, out);
}